// round 13
// baseline (speedup 1.0000x reference)
#include <cuda_runtime.h>
#include <cuda_fp16.h>
#include <math.h>
#include <stdint.h>

// ---------------- problem constants ----------------
#define B_   4
#define N0_  8192
#define D_   1024
#define H_   16
#define DH_  64
#define CB   32
#define LVLS 8
#define PYR_TOK 65280

// ---------------- device scratch ----------------
__device__ __half g_qh[(size_t)PYR_TOK * D_];
__device__ __half g_kh[(size_t)PYR_TOK * D_];
__device__ __half g_vh[(size_t)PYR_TOK * D_];
__device__ __half g_numh[(size_t)PYR_TOK * D_];
__device__ float  g_den[(size_t)PYR_TOK * H_];
__device__ float  g_m[PYR_TOK];
__device__ __half g_xq_h[(size_t)B_ * N0_ * D_];
__device__ __half g_xkv_h[(size_t)B_ * N0_ * D_];
__device__ __half g_att_h[(size_t)B_ * N0_ * D_];
__device__ __half g_wT_h[4 * (size_t)D_ * D_];

// ---------------- helpers ----------------
__device__ __forceinline__ uint32_t smem_cast(const void* p) {
    return (uint32_t)__cvta_generic_to_shared(p);
}
__device__ __forceinline__ void cpa16(uint32_t dst, const void* src) {
    asm volatile("cp.async.cg.shared.global [%0], [%1], 16;" :: "r"(dst), "l"(src));
}
#define CP_COMMIT() asm volatile("cp.async.commit_group;" ::: "memory")
#define CP_WAIT1()  asm volatile("cp.async.wait_group 1;" ::: "memory")
#define CP_WAIT0()  asm volatile("cp.async.wait_group 0;" ::: "memory")

__device__ __forceinline__ void ldsm4(uint32_t& r0, uint32_t& r1, uint32_t& r2, uint32_t& r3,
                                      uint32_t addr) {
    asm volatile("ldmatrix.sync.aligned.m8n8.x4.shared.b16 {%0,%1,%2,%3}, [%4];"
                 : "=r"(r0), "=r"(r1), "=r"(r2), "=r"(r3) : "r"(addr));
}
__device__ __forceinline__ void ldsm2t(uint32_t& r0, uint32_t& r1, uint32_t addr) {
    asm volatile("ldmatrix.sync.aligned.m8n8.x2.trans.shared.b16 {%0,%1}, [%2];"
                 : "=r"(r0), "=r"(r1) : "r"(addr));
}
__device__ __forceinline__ void mma_f16(float* c, const uint32_t* a, const uint32_t* b) {
    asm volatile(
        "mma.sync.aligned.m16n8k16.row.col.f32.f16.f16.f32 "
        "{%0,%1,%2,%3}, {%4,%5,%6,%7}, {%8,%9}, {%0,%1,%2,%3};"
        : "+f"(c[0]), "+f"(c[1]), "+f"(c[2]), "+f"(c[3])
        : "r"(a[0]), "r"(a[1]), "r"(a[2]), "r"(a[3]), "r"(b[0]), "r"(b[1]));
}

// ---------------- convert kernels ----------------
__global__ void cvt_x(const float* __restrict__ in, __half* __restrict__ out, int n4)
{
    int i = blockIdx.x * blockDim.x + threadIdx.x;
    if (i >= n4) return;
    float4 v = ((const float4*)in)[i];
    ((__half2*)out)[2 * i]     = __floats2half2_rn(v.x, v.y);
    ((__half2*)out)[2 * i + 1] = __floats2half2_rn(v.z, v.w);
}

__global__ void cvt_wT(const float* __restrict__ W0, const float* __restrict__ W1,
                       const float* __restrict__ W2, const float* __restrict__ W3,
                       __half* __restrict__ out)
{
    __shared__ float t[32][33];
    int z = blockIdx.z;
    const float* W = z == 0 ? W0 : z == 1 ? W1 : z == 2 ? W2 : W3;
    __half* o = out + (size_t)z * D_ * D_;
    int x0 = blockIdx.x * 32, y0 = blockIdx.y * 32;
    int tx = threadIdx.x, ty = threadIdx.y;
    #pragma unroll
    for (int i = 0; i < 4; i++)
        t[ty + i * 8][tx] = W[(size_t)(y0 + ty + i * 8) * D_ + x0 + tx];
    __syncthreads();
    #pragma unroll
    for (int i = 0; i < 4; i++)
        o[(size_t)(x0 + ty + i * 8) * D_ + y0 + tx] = __float2half(t[tx][ty + i * 8]);
}

// ---------------- fp16 GEMM: 128x128 CTA, 8 warps (2x4), warp tile m64n32, 3 CTA/SM ----
#define HSTR 72
#define HTILE (128 * HSTR)
#define GEMM_SMEM (4 * HTILE * 2)

__global__ __launch_bounds__(256, 3) void gemm_h(
    const __half* __restrict__ A, const __half* __restrict__ Bt,
    float* __restrict__ Co, __half* __restrict__ CoH,
    int M, int N, int K, float alpha,
    const float* __restrict__ bias, const int* __restrict__ rowmask)
{
    extern __shared__ __half smh[];
    __half* Abuf[2] = { smh,             smh + HTILE };
    __half* Bbuf[2] = { smh + 2 * HTILE, smh + 3 * HTILE };

    const int tid  = threadIdx.x;
    const int warp = tid >> 5;
    const int lane = tid & 31;
    const int wr   = warp >> 2;
    const int wc   = warp & 3;
    const int g    = lane >> 2;
    const int tig  = lane & 3;

    const int m0 = blockIdx.y * 128;
    const int n0 = blockIdx.x * 128;

    const int aRow = wr * 64 + ((lane >> 3) & 1) * 8 + (lane & 7);
    const int aCol = (lane >> 4) * 8;
    const int bRow = wc * 32 + (lane >> 4) * 8 + (lane & 7);
    const int bCol = ((lane >> 3) & 1) * 8;

    const uint32_t uA[2] = { smem_cast(Abuf[0]), smem_cast(Abuf[1]) };
    const uint32_t uB[2] = { smem_cast(Bbuf[0]), smem_cast(Bbuf[1]) };

    float acc[4][4][4];
    #pragma unroll
    for (int i = 0; i < 4; i++)
        #pragma unroll
        for (int j = 0; j < 4; j++)
            #pragma unroll
            for (int q = 0; q < 4; q++) acc[i][j][q] = 0.f;

    const int NIT = K / 64;

    auto load_tile = [&](int it, int s) {
        const int k0 = it * 64;
        #pragma unroll
        for (int i = 0; i < 4; i++) {
            int idx = tid + i * 256;
            int row = idx >> 3, c = idx & 7;
            uint32_t off = (uint32_t)(row * HSTR + c * 8) * 2;
            cpa16(uA[s] + off, A  + (size_t)(m0 + row) * K + k0 + c * 8);
            cpa16(uB[s] + off, Bt + (size_t)(n0 + row) * K + k0 + c * 8);
        }
        CP_COMMIT();
    };

    load_tile(0, 0);

    for (int it = 0; it < NIT; ++it) {
        const int s = it & 1;
        if (it + 1 < NIT) { load_tile(it + 1, s ^ 1); CP_WAIT1(); }
        else              { CP_WAIT0(); }
        __syncthreads();

        const uint32_t aB = uA[s] + (uint32_t)(aRow * HSTR + aCol) * 2;
        const uint32_t bB = uB[s] + (uint32_t)(bRow * HSTR + bCol) * 2;
        #pragma unroll
        for (int ks = 0; ks < 4; ks++) {
            uint32_t bfr[4][2];
            #pragma unroll
            for (int t = 0; t < 2; t++) {
                uint32_t r0, r1, r2, r3;
                ldsm4(r0, r1, r2, r3, bB + (uint32_t)(t * 16 * HSTR + ks * 16) * 2);
                bfr[2 * t][0] = r0; bfr[2 * t][1] = r1;
                bfr[2 * t + 1][0] = r2; bfr[2 * t + 1][1] = r3;
            }
            #pragma unroll
            for (int mf = 0; mf < 4; mf++) {
                uint32_t af[4];
                ldsm4(af[0], af[1], af[2], af[3],
                      aB + (uint32_t)(mf * 16 * HSTR + ks * 16) * 2);
                #pragma unroll
                for (int nf = 0; nf < 4; nf++)
                    mma_f16(acc[mf][nf], af, bfr[nf]);
            }
        }
        __syncthreads();
    }

    #pragma unroll
    for (int mf = 0; mf < 4; mf++) {
        int r0 = m0 + wr * 64 + mf * 16 + g;
        int r1 = r0 + 8;
        float mk0 = rowmask ? (float)rowmask[r0] : 1.f;
        float mk1 = rowmask ? (float)rowmask[r1] : 1.f;
        #pragma unroll
        for (int nf = 0; nf < 4; nf++) {
            int col = n0 + wc * 32 + nf * 8 + 2 * tig;
            float b0 = bias[col], b1 = bias[col + 1];
            float o00 = (acc[mf][nf][0] * alpha + b0) * mk0;
            float o01 = (acc[mf][nf][1] * alpha + b1) * mk0;
            float o10 = (acc[mf][nf][2] * alpha + b0) * mk1;
            float o11 = (acc[mf][nf][3] * alpha + b1) * mk1;
            if (CoH) {
                *(__half2*)(CoH + (size_t)r0 * N + col) = __floats2half2_rn(o00, o01);
                *(__half2*)(CoH + (size_t)r1 * N + col) = __floats2half2_rn(o10, o11);
            } else {
                *(float2*)(Co + (size_t)r0 * N + col) = make_float2(o00, o01);
                *(float2*)(Co + (size_t)r1 * N + col) = make_float2(o10, o11);
            }
        }
    }
}

// ---------------- mask init ----------------
__global__ void mask_init(const int* __restrict__ kmask, float* __restrict__ m0, int n)
{
    int i = blockIdx.x * blockDim.x + threadIdx.x;
    if (i < n) m0[i] = (float)kmask[i];
}

// ---------------- coarsen fp16 (q/k/v) ----------------
__global__ void coarsen_h(const __half* __restrict__ in, __half* __restrict__ out, int nl2)
{
    const int cols2 = D_ / 2;
    int i = blockIdx.x * blockDim.x + threadIdx.x;
    int total = B_ * nl2 * cols2;
    if (i >= total) return;
    int c2 = i % cols2;
    int n2 = (i / cols2) % nl2;
    int b  = i / (cols2 * nl2);
    size_t a = ((size_t)b * (2 * nl2) + 2 * n2) * cols2 + c2;
    float2 fa = __half22float2(((const __half2*)in)[a]);
    float2 fb = __half22float2(((const __half2*)in)[a + cols2]);
    ((__half2*)out)[i] = __floats2half2_rn(0.5f * (fa.x + fb.x), 0.5f * (fa.y + fb.y));
}

// ---------------- coarsen fp32 (mask) ----------------
__global__ void coarsen_m(const float* __restrict__ in, float* __restrict__ out, int nl2)
{
    int i = blockIdx.x * blockDim.x + threadIdx.x;
    if (i >= B_ * nl2) return;
    int n2 = i % nl2;
    int b  = i / nl2;
    size_t a = (size_t)b * (2 * nl2) + 2 * n2;
    out[i] = 0.5f * (in[a] + in[a + 1]);
}

// ---------------- hierarchical windowed attention: fp16 in/out ----------------
#define QSTR 72
#define KSTR 72
#define VSTR 72
#define PSTR 104

__global__ __launch_bounds__(128) void hier_attn(
    const __half* __restrict__ qL, const __half* __restrict__ kL, const __half* __restrict__ vL,
    const float* __restrict__ mL, const float* __restrict__ rpbL,
    __half* __restrict__ numL, float* __restrict__ denL, int nl, int lvl)
{
    __shared__ __half Qh[32 * QSTR];
    __shared__ __half Kh[96 * KSTR];
    __shared__ __half Vh[96 * VSTR];
    __shared__ __half Ph[32 * PSTR];
    __shared__ float srpb[128];
    __shared__ float smw[96];
    __shared__ float sden[32];

    const int blk = blockIdx.x, h = blockIdx.y, b = blockIdx.z;
    const int tid = threadIdx.x;
    const int warp = tid >> 5;
    const int lane = tid & 31;
    const int g = lane >> 2, tig = lane & 3;
    const int mtile = warp >> 1;
    const int nh = warp & 1;

    const __half* qbase = qL + ((size_t)b * nl + (size_t)blk * CB) * D_ + h * DH_;
    for (int i = tid; i < 32 * 8; i += 128) {
        int qi = i >> 3, d8 = (i & 7) * 8;
        *(uint4*)&Qh[qi * QSTR + d8] = *(const uint4*)(qbase + (size_t)qi * D_ + d8);
    }
    const uint4 z4 = make_uint4(0, 0, 0, 0);
    for (int i = tid; i < 96 * 8; i += 128) {
        int p = i >> 3, d8 = (i & 7) * 8;
        int n = blk * CB + p - CB;
        uint4 kv = z4, vv = z4;
        if (n >= 0 && n < nl) {
            size_t off = ((size_t)b * nl + n) * D_ + h * DH_ + d8;
            kv = *(const uint4*)(kL + off);
            vv = *(const uint4*)(vL + off);
        }
        *(uint4*)&Kh[p * KSTR + d8] = kv;
        *(uint4*)&Vh[p * VSTR + d8] = vv;
    }
    for (int p = tid; p < 96; p += 128) {
        int n = blk * CB + p - CB;
        smw[p] = (n >= 0 && n < nl) ? mL[(size_t)b * nl + n] : 0.f;
    }
    for (int i = tid; i < 127; i += 128) srpb[i] = rpbL[h * 127 + i];
    if (tid < 32) sden[tid] = 0.f;
    __syncthreads();

    // phase 1: logits
    float c1[6][4];
    #pragma unroll
    for (int t = 0; t < 6; t++)
        #pragma unroll
        for (int q = 0; q < 4; q++) c1[t][q] = 0.f;

    const uint32_t qAddr = smem_cast(Qh) +
        (uint32_t)((mtile * 16 + ((lane >> 3) & 1) * 8 + (lane & 7)) * QSTR + (lane >> 4) * 8) * 2;
    const uint32_t kAddrBase = smem_cast(Kh);
    const int kRow = (lane >> 4) * 8 + (lane & 7);
    const int kColH = ((lane >> 3) & 1) * 8;

    #pragma unroll
    for (int ks = 0; ks < 4; ks++) {
        uint32_t a[4];
        ldsm4(a[0], a[1], a[2], a[3], qAddr + (uint32_t)(ks * 16) * 2);
        #pragma unroll
        for (int t = 0; t < 3; t++) {
            int prow = nh * 48 + t * 16 + kRow;
            uint32_t r0, r1, r2, r3;
            ldsm4(r0, r1, r2, r3,
                  kAddrBase + (uint32_t)(prow * KSTR + kColH + ks * 16) * 2);
            uint32_t b0[2] = { r0, r1 }, b1[2] = { r2, r3 };
            mma_f16(c1[2 * t],     a, b0);
            mma_f16(c1[2 * t + 1], a, b1);
        }
    }

    // epilogue -> P, den
    {
        const int row0 = mtile * 16 + g;
        const int row1 = row0 + 8;
        float rs0 = 0.f, rs1 = 0.f;
        #pragma unroll
        for (int t = 0; t < 6; t++) {
            int p0 = nh * 48 + (t >> 1) * 16 + (t & 1) * 8 + 2 * tig;
            #pragma unroll
            for (int half = 0; half < 2; half++) {
                int row = half ? row1 : row0;
                float w0, w1;
                #pragma unroll
                for (int j = 0; j < 2; j++) {
                    int p = p0 + j;
                    float lg = c1[t][half * 2 + j] + srpb[p - row + CB - 1];
                    float valid = 1.f;
                    if (lvl > 0) {
                        int bk3 = p >> 5, pl = p & 31;
                        bool inv = (bk3 == 1) ||
                                   (bk3 == 0 && row < 16 && pl >= 16) ||
                                   (bk3 == 2 && row >= 16 && pl < 16);
                        valid = inv ? 0.f : 1.f;
                    }
                    float w = expf(lg) * valid * smw[p];
                    __half wh = __float2half_rn(w);
                    float wr = __half2float(wh);
                    if (j == 0) w0 = wr; else w1 = wr;
                }
                *(__half2*)&Ph[row * PSTR + p0] = __floats2half2_rn(w0, w1);
                if (half) rs1 += w0 + w1; else rs0 += w0 + w1;
            }
        }
        rs0 += __shfl_xor_sync(0xFFFFFFFF, rs0, 1);
        rs0 += __shfl_xor_sync(0xFFFFFFFF, rs0, 2);
        rs1 += __shfl_xor_sync(0xFFFFFFFF, rs1, 1);
        rs1 += __shfl_xor_sync(0xFFFFFFFF, rs1, 2);
        if (tig == 0) {
            atomicAdd(&sden[row0], rs0);
            atomicAdd(&sden[row1], rs1);
        }
    }
    __syncthreads();

    if (tid < 32)
        denL[((size_t)b * nl + blk * CB + tid) * H_ + h] = sden[tid];

    // phase 2: num = P @ V
    float c2[4][4];
    #pragma unroll
    for (int t = 0; t < 4; t++)
        #pragma unroll
        for (int q = 0; q < 4; q++) c2[t][q] = 0.f;

    const uint32_t pAddr = smem_cast(Ph) +
        (uint32_t)((mtile * 16 + ((lane >> 3) & 1) * 8 + (lane & 7)) * PSTR + (lane >> 4) * 8) * 2;
    const uint32_t vAddrBase = smem_cast(Vh);
    const int dhalf = nh * 32;

    #pragma unroll
    for (int ks = 0; ks < 6; ks++) {
        uint32_t a[4];
        ldsm4(a[0], a[1], a[2], a[3], pAddr + (uint32_t)(ks * 16) * 2);
        #pragma unroll
        for (int t = 0; t < 4; t++) {
            uint32_t b[2];
            ldsm2t(b[0], b[1],
                   vAddrBase + (uint32_t)((ks * 16 + (lane & 15)) * VSTR + dhalf + t * 8) * 2);
            mma_f16(c2[t], a, b);
        }
    }

    // write num (fp16)
    {
        int row0 = blk * CB + mtile * 16 + g;
        __half* base = numL + ((size_t)b * nl + row0) * D_ + h * DH_;
        #pragma unroll
        for (int t = 0; t < 4; t++) {
            int col = dhalf + t * 8 + 2 * tig;
            *(__half2*)(base + col)          = __floats2half2_rn(c2[t][0], c2[t][1]);
            *(__half2*)(base + 8 * D_ + col) = __floats2half2_rn(c2[t][2], c2[t][3]);
        }
    }
}

// ---------------- combine: block per (b,n) row ----------------
__global__ __launch_bounds__(256) void combine(
    const __half* __restrict__ num, const float* __restrict__ den,
    const int* __restrict__ qmask, __half* __restrict__ att)
{
    __shared__ float dinv[16];
    __shared__ float sq;
    const int bn = blockIdx.x;
    const int b = bn >> 13;
    const int n = bn & (N0_ - 1);
    const int tid = threadIdx.x;

    if (tid < 16) {
        float s = 0.f;
        size_t toff = 0;
        #pragma unroll
        for (int l = 0; l < LVLS; l++) {
            int nl = N0_ >> l;
            s += den[(toff + (size_t)b * nl + (n >> l)) * H_ + tid];
            toff += (size_t)B_ * nl;
        }
        dinv[tid] = 1.f / (s + 1e-9f);
    }
    if (tid == 0) sq = (float)qmask[bn];
    __syncthreads();

    const int e0 = tid * 4;
    const int h = e0 >> 6;
    float a0 = 0.f, a1 = 0.f, a2 = 0.f, a3 = 0.f;
    size_t toff = 0;
    #pragma unroll
    for (int l = 0; l < LVLS; l++) {
        int nl = N0_ >> l;
        size_t tk = toff + (size_t)b * nl + (n >> l);
        uint2 u = *(const uint2*)(num + tk * D_ + e0);
        float2 f0 = __half22float2(*(__half2*)&u.x);
        float2 f1 = __half22float2(*(__half2*)&u.y);
        a0 += f0.x; a1 += f0.y; a2 += f1.x; a3 += f1.y;
        toff += (size_t)B_ * nl;
    }
    float s = dinv[h] * sq;
    __half2 o0 = __floats2half2_rn(a0 * s, a1 * s);
    __half2 o1 = __floats2half2_rn(a2 * s, a3 * s);
    *(uint2*)(att + (size_t)bn * D_ + e0) =
        make_uint2(*(uint32_t*)&o0, *(uint32_t*)&o1);
}

// ---------------- host launch ----------------
extern "C" void kernel_launch(void* const* d_in, const int* in_sizes, int n_in,
                              void* d_out, int out_size)
{
    const float* inputs_q  = (const float*)d_in[0];
    const float* inputs_kv = (const float*)d_in[1];
    const int*   qmask     = (const int*)d_in[2];
    const int*   kmask     = (const int*)d_in[3];
    const float* Wq        = (const float*)d_in[4];
    const float* bq        = (const float*)d_in[5];
    const float* Wk        = (const float*)d_in[6];
    const float* bk        = (const float*)d_in[7];
    const float* Wv        = (const float*)d_in[8];
    const float* bv        = (const float*)d_in[9];
    const float* Wo        = (const float*)d_in[10];
    const float* bo        = (const float*)d_in[11];
    const float* rpb       = (const float*)d_in[12];
    float* out             = (float*)d_out;

    float *denp, *mp;
    __half *qph, *kph, *vph, *numh, *xqh, *xkvh, *atth, *wTh;
    cudaGetSymbolAddress((void**)&qph,  g_qh);
    cudaGetSymbolAddress((void**)&kph,  g_kh);
    cudaGetSymbolAddress((void**)&vph,  g_vh);
    cudaGetSymbolAddress((void**)&numh, g_numh);
    cudaGetSymbolAddress((void**)&denp, g_den);
    cudaGetSymbolAddress((void**)&mp,   g_m);
    cudaGetSymbolAddress((void**)&xqh,  g_xq_h);
    cudaGetSymbolAddress((void**)&xkvh, g_xkv_h);
    cudaGetSymbolAddress((void**)&atth, g_att_h);
    cudaGetSymbolAddress((void**)&wTh,  g_wT_h);

    cudaFuncSetAttribute(gemm_h, cudaFuncAttributeMaxDynamicSharedMemorySize, GEMM_SMEM);

    const int M = B_ * N0_;
    const float scale = 0.125f;

    mask_init<<<(B_ * N0_ + 255) / 256, 256>>>(kmask, mp, B_ * N0_);

    int n4 = M * D_ / 4;
    cvt_x<<<(n4 + 255) / 256, 256>>>(inputs_q,  xqh,  n4);
    cvt_x<<<(n4 + 255) / 256, 256>>>(inputs_kv, xkvh, n4);
    dim3 wtg(D_ / 32, D_ / 32, 4);
    cvt_wT<<<wtg, dim3(32, 8)>>>(Wq, Wk, Wv, Wo, wTh);

    dim3 gemmGrid(D_ / 128, M / 128);
    const size_t WSZ = (size_t)D_ * D_;
    gemm_h<<<gemmGrid, 256, GEMM_SMEM>>>(xqh,  wTh,           nullptr, qph, M, D_, D_, scale, bq, nullptr);
    gemm_h<<<gemmGrid, 256, GEMM_SMEM>>>(xkvh, wTh + WSZ,     nullptr, kph, M, D_, D_, 1.f, bk, nullptr);
    gemm_h<<<gemmGrid, 256, GEMM_SMEM>>>(xkvh, wTh + 2 * WSZ, nullptr, vph, M, D_, D_, 1.f, bv, kmask);

    size_t toff = 0;
    int nl = N0_;
    for (int l = 0; l < LVLS; l++) {
        dim3 ag(nl / CB, H_, B_);
        hier_attn<<<ag, 128>>>(
            qph + toff * D_, kph + toff * D_, vph + toff * D_, mp + toff,
            rpb + (size_t)l * H_ * (4 * CB - 1),
            numh + toff * D_, denp + toff * H_, nl, l);
        if (l < LVLS - 1) {
            int nl2 = nl / 2;
            size_t toff2 = toff + (size_t)B_ * nl;
            int tot2 = B_ * nl2 * (D_ / 2);
            coarsen_h<<<(tot2 + 255) / 256, 256>>>(qph + toff * D_, qph + toff2 * D_, nl2);
            coarsen_h<<<(tot2 + 255) / 256, 256>>>(kph + toff * D_, kph + toff2 * D_, nl2);
            coarsen_h<<<(tot2 + 255) / 256, 256>>>(vph + toff * D_, vph + toff2 * D_, nl2);
            int totm = B_ * nl2;
            coarsen_m<<<(totm + 255) / 256, 256>>>(mp + toff, mp + toff2, nl2);
        }
        toff += (size_t)B_ * nl;
        nl >>= 1;
    }

    combine<<<B_ * N0_, 256>>>(numh, denp, qmask, atth);

    gemm_h<<<gemmGrid, 256, GEMM_SMEM>>>(atth, wTh + 3 * WSZ, out, nullptr, M, D_, D_, 1.f, bo, nullptr);
}

// round 14
// speedup vs baseline: 1.3401x; 1.3401x over previous
#include <cuda_runtime.h>
#include <cuda_fp16.h>
#include <math.h>
#include <stdint.h>

// ---------------- problem constants ----------------
#define B_   4
#define N0_  8192
#define D_   1024
#define H_   16
#define DH_  64
#define CB   32
#define LVLS 8
#define PYR_TOK 65280

// ---------------- device scratch ----------------
__device__ __half g_qh[(size_t)PYR_TOK * D_];
__device__ __half g_kh[(size_t)PYR_TOK * D_];
__device__ __half g_vh[(size_t)PYR_TOK * D_];
__device__ __half g_numh[(size_t)PYR_TOK * D_];
__device__ float  g_den[(size_t)PYR_TOK * H_];
__device__ float  g_m[PYR_TOK];
__device__ __half g_xq_h[(size_t)B_ * N0_ * D_];
__device__ __half g_xkv_h[(size_t)B_ * N0_ * D_];
__device__ __half g_att_h[(size_t)B_ * N0_ * D_];
__device__ __half g_wT_h[4 * (size_t)D_ * D_];

// ---------------- helpers ----------------
__device__ __forceinline__ uint32_t smem_cast(const void* p) {
    return (uint32_t)__cvta_generic_to_shared(p);
}
__device__ __forceinline__ void cpa16(uint32_t dst, const void* src) {
    asm volatile("cp.async.cg.shared.global [%0], [%1], 16;" :: "r"(dst), "l"(src));
}
#define CP_COMMIT() asm volatile("cp.async.commit_group;" ::: "memory")
#define CP_WAIT1()  asm volatile("cp.async.wait_group 1;" ::: "memory")
#define CP_WAIT0()  asm volatile("cp.async.wait_group 0;" ::: "memory")

__device__ __forceinline__ void ldsm4(uint32_t& r0, uint32_t& r1, uint32_t& r2, uint32_t& r3,
                                      uint32_t addr) {
    asm volatile("ldmatrix.sync.aligned.m8n8.x4.shared.b16 {%0,%1,%2,%3}, [%4];"
                 : "=r"(r0), "=r"(r1), "=r"(r2), "=r"(r3) : "r"(addr));
}
__device__ __forceinline__ void ldsm2t(uint32_t& r0, uint32_t& r1, uint32_t addr) {
    asm volatile("ldmatrix.sync.aligned.m8n8.x2.trans.shared.b16 {%0,%1}, [%2];"
                 : "=r"(r0), "=r"(r1) : "r"(addr));
}
__device__ __forceinline__ void mma_f16(float* c, const uint32_t* a, const uint32_t* b) {
    asm volatile(
        "mma.sync.aligned.m16n8k16.row.col.f32.f16.f16.f32 "
        "{%0,%1,%2,%3}, {%4,%5,%6,%7}, {%8,%9}, {%0,%1,%2,%3};"
        : "+f"(c[0]), "+f"(c[1]), "+f"(c[2]), "+f"(c[3])
        : "r"(a[0]), "r"(a[1]), "r"(a[2]), "r"(a[3]), "r"(b[0]), "r"(b[1]));
}

// ---------------- convert kernels ----------------
__global__ void cvt_x(const float* __restrict__ in, __half* __restrict__ out, int n4)
{
    int i = blockIdx.x * blockDim.x + threadIdx.x;
    if (i >= n4) return;
    float4 v = ((const float4*)in)[i];
    ((__half2*)out)[2 * i]     = __floats2half2_rn(v.x, v.y);
    ((__half2*)out)[2 * i + 1] = __floats2half2_rn(v.z, v.w);
}

__global__ void cvt_wT(const float* __restrict__ W0, const float* __restrict__ W1,
                       const float* __restrict__ W2, const float* __restrict__ W3,
                       __half* __restrict__ out)
{
    __shared__ float t[32][33];
    int z = blockIdx.z;
    const float* W = z == 0 ? W0 : z == 1 ? W1 : z == 2 ? W2 : W3;
    __half* o = out + (size_t)z * D_ * D_;
    int x0 = blockIdx.x * 32, y0 = blockIdx.y * 32;
    int tx = threadIdx.x, ty = threadIdx.y;
    #pragma unroll
    for (int i = 0; i < 4; i++)
        t[ty + i * 8][tx] = W[(size_t)(y0 + ty + i * 8) * D_ + x0 + tx];
    __syncthreads();
    #pragma unroll
    for (int i = 0; i < 4; i++)
        o[(size_t)(x0 + ty + i * 8) * D_ + y0 + tx] = __float2half(t[tx][ty + i * 8]);
}

// ---------------- fp16 GEMM (R11 config: 256 thr, 2 CTA/SM) ----------------
#define HSTR 72
#define HTILE (128 * HSTR)
#define GEMM_SMEM (4 * HTILE * 2)

__global__ __launch_bounds__(256, 2) void gemm_h(
    const __half* __restrict__ A, const __half* __restrict__ Bt,
    float* __restrict__ Co, __half* __restrict__ CoH,
    int M, int N, int K, float alpha,
    const float* __restrict__ bias, const int* __restrict__ rowmask)
{
    extern __shared__ __half smh[];
    __half* Abuf[2] = { smh,             smh + HTILE };
    __half* Bbuf[2] = { smh + 2 * HTILE, smh + 3 * HTILE };

    const int tid  = threadIdx.x;
    const int warp = tid >> 5;
    const int lane = tid & 31;
    const int wr   = warp >> 2;
    const int wc   = warp & 3;
    const int g    = lane >> 2;
    const int tig  = lane & 3;

    const int m0 = blockIdx.y * 128;
    const int n0 = blockIdx.x * 128;

    const int aRow = wr * 64 + ((lane >> 3) & 1) * 8 + (lane & 7);
    const int aCol = (lane >> 4) * 8;
    const int bRow = wc * 32 + (lane >> 4) * 8 + (lane & 7);
    const int bCol = ((lane >> 3) & 1) * 8;

    const uint32_t uA[2] = { smem_cast(Abuf[0]), smem_cast(Abuf[1]) };
    const uint32_t uB[2] = { smem_cast(Bbuf[0]), smem_cast(Bbuf[1]) };

    float acc[4][4][4];
    #pragma unroll
    for (int i = 0; i < 4; i++)
        #pragma unroll
        for (int j = 0; j < 4; j++)
            #pragma unroll
            for (int q = 0; q < 4; q++) acc[i][j][q] = 0.f;

    const int NIT = K / 64;

    auto load_tile = [&](int it, int s) {
        const int k0 = it * 64;
        #pragma unroll
        for (int i = 0; i < 4; i++) {
            int idx = tid + i * 256;
            int row = idx >> 3, c = idx & 7;
            uint32_t off = (uint32_t)(row * HSTR + c * 8) * 2;
            cpa16(uA[s] + off, A  + (size_t)(m0 + row) * K + k0 + c * 8);
            cpa16(uB[s] + off, Bt + (size_t)(n0 + row) * K + k0 + c * 8);
        }
        CP_COMMIT();
    };

    load_tile(0, 0);

    for (int it = 0; it < NIT; ++it) {
        const int s = it & 1;
        if (it + 1 < NIT) { load_tile(it + 1, s ^ 1); CP_WAIT1(); }
        else              { CP_WAIT0(); }
        __syncthreads();

        const uint32_t aB = uA[s] + (uint32_t)(aRow * HSTR + aCol) * 2;
        const uint32_t bB = uB[s] + (uint32_t)(bRow * HSTR + bCol) * 2;
        #pragma unroll
        for (int ks = 0; ks < 4; ks++) {
            uint32_t bfr[4][2];
            #pragma unroll
            for (int t = 0; t < 2; t++) {
                uint32_t r0, r1, r2, r3;
                ldsm4(r0, r1, r2, r3, bB + (uint32_t)(t * 16 * HSTR + ks * 16) * 2);
                bfr[2 * t][0] = r0; bfr[2 * t][1] = r1;
                bfr[2 * t + 1][0] = r2; bfr[2 * t + 1][1] = r3;
            }
            #pragma unroll
            for (int mf = 0; mf < 4; mf++) {
                uint32_t af[4];
                ldsm4(af[0], af[1], af[2], af[3],
                      aB + (uint32_t)(mf * 16 * HSTR + ks * 16) * 2);
                #pragma unroll
                for (int nf = 0; nf < 4; nf++)
                    mma_f16(acc[mf][nf], af, bfr[nf]);
            }
        }
        __syncthreads();
    }

    #pragma unroll
    for (int mf = 0; mf < 4; mf++) {
        int r0 = m0 + wr * 64 + mf * 16 + g;
        int r1 = r0 + 8;
        float mk0 = rowmask ? (float)rowmask[r0] : 1.f;
        float mk1 = rowmask ? (float)rowmask[r1] : 1.f;
        #pragma unroll
        for (int nf = 0; nf < 4; nf++) {
            int col = n0 + wc * 32 + nf * 8 + 2 * tig;
            float b0 = bias[col], b1 = bias[col + 1];
            float o00 = (acc[mf][nf][0] * alpha + b0) * mk0;
            float o01 = (acc[mf][nf][1] * alpha + b1) * mk0;
            float o10 = (acc[mf][nf][2] * alpha + b0) * mk1;
            float o11 = (acc[mf][nf][3] * alpha + b1) * mk1;
            if (CoH) {
                *(__half2*)(CoH + (size_t)r0 * N + col) = __floats2half2_rn(o00, o01);
                *(__half2*)(CoH + (size_t)r1 * N + col) = __floats2half2_rn(o10, o11);
            } else {
                *(float2*)(Co + (size_t)r0 * N + col) = make_float2(o00, o01);
                *(float2*)(Co + (size_t)r1 * N + col) = make_float2(o10, o11);
            }
        }
    }
}

// ---------------- mask init ----------------
__global__ void mask_init(const int* __restrict__ kmask, float* __restrict__ m0, int n)
{
    int i = blockIdx.x * blockDim.x + threadIdx.x;
    if (i < n) m0[i] = (float)kmask[i];
}

// ---------------- coarsen fp16 (q/k/v) ----------------
__global__ void coarsen_h(const __half* __restrict__ in, __half* __restrict__ out, int nl2)
{
    const int cols2 = D_ / 2;
    int i = blockIdx.x * blockDim.x + threadIdx.x;
    int total = B_ * nl2 * cols2;
    if (i >= total) return;
    int c2 = i % cols2;
    int n2 = (i / cols2) % nl2;
    int b  = i / (cols2 * nl2);
    size_t a = ((size_t)b * (2 * nl2) + 2 * n2) * cols2 + c2;
    float2 fa = __half22float2(((const __half2*)in)[a]);
    float2 fb = __half22float2(((const __half2*)in)[a + cols2]);
    ((__half2*)out)[i] = __floats2half2_rn(0.5f * (fa.x + fb.x), 0.5f * (fa.y + fb.y));
}

// ---------------- coarsen fp32 (mask) ----------------
__global__ void coarsen_m(const float* __restrict__ in, float* __restrict__ out, int nl2)
{
    int i = blockIdx.x * blockDim.x + threadIdx.x;
    if (i >= B_ * nl2) return;
    int n2 = i % nl2;
    int b  = i / nl2;
    size_t a = (size_t)b * (2 * nl2) + 2 * n2;
    out[i] = 0.5f * (in[a] + in[a + 1]);
}

// ---------------- fused hierarchical attention: ALL levels in one launch ----------------
// grid: (510, H, B). blockIdx.x -> (lvl, blk): level l occupies 256>>l consecutive x-blocks.
#define QSTR 72
#define KSTR 72
#define VSTR 72
#define PSTR 104

__global__ __launch_bounds__(128) void hier_attn_all(
    const __half* __restrict__ qP, const __half* __restrict__ kP, const __half* __restrict__ vP,
    const float* __restrict__ mP, const float* __restrict__ rpb,
    __half* __restrict__ numP, float* __restrict__ denP)
{
    __shared__ __half Qh[32 * QSTR];
    __shared__ __half Kh[96 * KSTR];
    __shared__ __half Vh[96 * VSTR];
    __shared__ __half Ph[32 * PSTR];
    __shared__ float srpb[128];
    __shared__ float smw[96];
    __shared__ float sden[32];

    // map blockIdx.x -> (lvl, blk)
    int bx = blockIdx.x;
    int lvl = 0, nb = N0_ / CB;            // 256
    while (bx >= nb) { bx -= nb; nb >>= 1; lvl++; }
    const int blk = bx;
    const int nl = N0_ >> lvl;
    const size_t toff = (size_t)B_ * (2 * N0_ - 2 * (N0_ >> lvl));

    const __half* qL = qP + toff * D_;
    const __half* kL = kP + toff * D_;
    const __half* vL = vP + toff * D_;
    const float*  mL = mP + toff;
    const float*  rpbL = rpb + (size_t)lvl * H_ * (4 * CB - 1);
    __half* numL = numP + toff * D_;
    float*  denL = denP + toff * H_;

    const int h = blockIdx.y, b = blockIdx.z;
    const int tid = threadIdx.x;
    const int warp = tid >> 5;
    const int lane = tid & 31;
    const int g = lane >> 2, tig = lane & 3;
    const int mtile = warp >> 1;
    const int nh = warp & 1;

    const __half* qbase = qL + ((size_t)b * nl + (size_t)blk * CB) * D_ + h * DH_;
    for (int i = tid; i < 32 * 8; i += 128) {
        int qi = i >> 3, d8 = (i & 7) * 8;
        *(uint4*)&Qh[qi * QSTR + d8] = *(const uint4*)(qbase + (size_t)qi * D_ + d8);
    }
    const uint4 z4 = make_uint4(0, 0, 0, 0);
    for (int i = tid; i < 96 * 8; i += 128) {
        int p = i >> 3, d8 = (i & 7) * 8;
        int n = blk * CB + p - CB;
        uint4 kv = z4, vv = z4;
        if (n >= 0 && n < nl) {
            size_t off = ((size_t)b * nl + n) * D_ + h * DH_ + d8;
            kv = *(const uint4*)(kL + off);
            vv = *(const uint4*)(vL + off);
        }
        *(uint4*)&Kh[p * KSTR + d8] = kv;
        *(uint4*)&Vh[p * VSTR + d8] = vv;
    }
    for (int p = tid; p < 96; p += 128) {
        int n = blk * CB + p - CB;
        smw[p] = (n >= 0 && n < nl) ? mL[(size_t)b * nl + n] : 0.f;
    }
    for (int i = tid; i < 127; i += 128) srpb[i] = rpbL[h * 127 + i];
    if (tid < 32) sden[tid] = 0.f;
    __syncthreads();

    // phase 1: logits
    float c1[6][4];
    #pragma unroll
    for (int t = 0; t < 6; t++)
        #pragma unroll
        for (int q = 0; q < 4; q++) c1[t][q] = 0.f;

    const uint32_t qAddr = smem_cast(Qh) +
        (uint32_t)((mtile * 16 + ((lane >> 3) & 1) * 8 + (lane & 7)) * QSTR + (lane >> 4) * 8) * 2;
    const uint32_t kAddrBase = smem_cast(Kh);
    const int kRow = (lane >> 4) * 8 + (lane & 7);
    const int kColH = ((lane >> 3) & 1) * 8;

    #pragma unroll
    for (int ks = 0; ks < 4; ks++) {
        uint32_t a[4];
        ldsm4(a[0], a[1], a[2], a[3], qAddr + (uint32_t)(ks * 16) * 2);
        #pragma unroll
        for (int t = 0; t < 3; t++) {
            int prow = nh * 48 + t * 16 + kRow;
            uint32_t r0, r1, r2, r3;
            ldsm4(r0, r1, r2, r3,
                  kAddrBase + (uint32_t)(prow * KSTR + kColH + ks * 16) * 2);
            uint32_t b0[2] = { r0, r1 }, b1[2] = { r2, r3 };
            mma_f16(c1[2 * t],     a, b0);
            mma_f16(c1[2 * t + 1], a, b1);
        }
    }

    // epilogue -> P, den
    {
        const int row0 = mtile * 16 + g;
        const int row1 = row0 + 8;
        float rs0 = 0.f, rs1 = 0.f;
        #pragma unroll
        for (int t = 0; t < 6; t++) {
            int p0 = nh * 48 + (t >> 1) * 16 + (t & 1) * 8 + 2 * tig;
            #pragma unroll
            for (int half = 0; half < 2; half++) {
                int row = half ? row1 : row0;
                float w0, w1;
                #pragma unroll
                for (int j = 0; j < 2; j++) {
                    int p = p0 + j;
                    float lg = c1[t][half * 2 + j] + srpb[p - row + CB - 1];
                    float valid = 1.f;
                    if (lvl > 0) {
                        int bk3 = p >> 5, pl = p & 31;
                        bool inv = (bk3 == 1) ||
                                   (bk3 == 0 && row < 16 && pl >= 16) ||
                                   (bk3 == 2 && row >= 16 && pl < 16);
                        valid = inv ? 0.f : 1.f;
                    }
                    float w = expf(lg) * valid * smw[p];
                    __half wh = __float2half_rn(w);
                    float wr = __half2float(wh);
                    if (j == 0) w0 = wr; else w1 = wr;
                }
                *(__half2*)&Ph[row * PSTR + p0] = __floats2half2_rn(w0, w1);
                if (half) rs1 += w0 + w1; else rs0 += w0 + w1;
            }
        }
        rs0 += __shfl_xor_sync(0xFFFFFFFF, rs0, 1);
        rs0 += __shfl_xor_sync(0xFFFFFFFF, rs0, 2);
        rs1 += __shfl_xor_sync(0xFFFFFFFF, rs1, 1);
        rs1 += __shfl_xor_sync(0xFFFFFFFF, rs1, 2);
        if (tig == 0) {
            atomicAdd(&sden[row0], rs0);
            atomicAdd(&sden[row1], rs1);
        }
    }
    __syncthreads();

    if (tid < 32)
        denL[((size_t)b * nl + blk * CB + tid) * H_ + h] = sden[tid];

    // phase 2: num = P @ V
    float c2[4][4];
    #pragma unroll
    for (int t = 0; t < 4; t++)
        #pragma unroll
        for (int q = 0; q < 4; q++) c2[t][q] = 0.f;

    const uint32_t pAddr = smem_cast(Ph) +
        (uint32_t)((mtile * 16 + ((lane >> 3) & 1) * 8 + (lane & 7)) * PSTR + (lane >> 4) * 8) * 2;
    const uint32_t vAddrBase = smem_cast(Vh);
    const int dhalf = nh * 32;

    #pragma unroll
    for (int ks = 0; ks < 6; ks++) {
        uint32_t a[4];
        ldsm4(a[0], a[1], a[2], a[3], pAddr + (uint32_t)(ks * 16) * 2);
        #pragma unroll
        for (int t = 0; t < 4; t++) {
            uint32_t b[2];
            ldsm2t(b[0], b[1],
                   vAddrBase + (uint32_t)((ks * 16 + (lane & 15)) * VSTR + dhalf + t * 8) * 2);
            mma_f16(c2[t], a, b);
        }
    }

    // write num (fp16)
    {
        int row0 = blk * CB + mtile * 16 + g;
        __half* base = numL + ((size_t)b * nl + row0) * D_ + h * DH_;
        #pragma unroll
        for (int t = 0; t < 4; t++) {
            int col = dhalf + t * 8 + 2 * tig;
            *(__half2*)(base + col)          = __floats2half2_rn(c2[t][0], c2[t][1]);
            *(__half2*)(base + 8 * D_ + col) = __floats2half2_rn(c2[t][2], c2[t][3]);
        }
    }
}

// ---------------- combine: block per (b,n) row ----------------
__global__ __launch_bounds__(256) void combine(
    const __half* __restrict__ num, const float* __restrict__ den,
    const int* __restrict__ qmask, __half* __restrict__ att)
{
    __shared__ float dinv[16];
    __shared__ float sq;
    const int bn = blockIdx.x;
    const int b = bn >> 13;
    const int n = bn & (N0_ - 1);
    const int tid = threadIdx.x;

    if (tid < 16) {
        float s = 0.f;
        size_t toff = 0;
        #pragma unroll
        for (int l = 0; l < LVLS; l++) {
            int nl = N0_ >> l;
            s += den[(toff + (size_t)b * nl + (n >> l)) * H_ + tid];
            toff += (size_t)B_ * nl;
        }
        dinv[tid] = 1.f / (s + 1e-9f);
    }
    if (tid == 0) sq = (float)qmask[bn];
    __syncthreads();

    const int e0 = tid * 4;
    const int h = e0 >> 6;
    float a0 = 0.f, a1 = 0.f, a2 = 0.f, a3 = 0.f;
    size_t toff = 0;
    #pragma unroll
    for (int l = 0; l < LVLS; l++) {
        int nl = N0_ >> l;
        size_t tk = toff + (size_t)b * nl + (n >> l);
        uint2 u = *(const uint2*)(num + tk * D_ + e0);
        float2 f0 = __half22float2(*(__half2*)&u.x);
        float2 f1 = __half22float2(*(__half2*)&u.y);
        a0 += f0.x; a1 += f0.y; a2 += f1.x; a3 += f1.y;
        toff += (size_t)B_ * nl;
    }
    float s = dinv[h] * sq;
    __half2 o0 = __floats2half2_rn(a0 * s, a1 * s);
    __half2 o1 = __floats2half2_rn(a2 * s, a3 * s);
    *(uint2*)(att + (size_t)bn * D_ + e0) =
        make_uint2(*(uint32_t*)&o0, *(uint32_t*)&o1);
}

// ---------------- host launch ----------------
extern "C" void kernel_launch(void* const* d_in, const int* in_sizes, int n_in,
                              void* d_out, int out_size)
{
    const float* inputs_q  = (const float*)d_in[0];
    const float* inputs_kv = (const float*)d_in[1];
    const int*   qmask     = (const int*)d_in[2];
    const int*   kmask     = (const int*)d_in[3];
    const float* Wq        = (const float*)d_in[4];
    const float* bq        = (const float*)d_in[5];
    const float* Wk        = (const float*)d_in[6];
    const float* bk        = (const float*)d_in[7];
    const float* Wv        = (const float*)d_in[8];
    const float* bv        = (const float*)d_in[9];
    const float* Wo        = (const float*)d_in[10];
    const float* bo        = (const float*)d_in[11];
    const float* rpb       = (const float*)d_in[12];
    float* out             = (float*)d_out;

    float *denp, *mp;
    __half *qph, *kph, *vph, *numh, *xqh, *xkvh, *atth, *wTh;
    cudaGetSymbolAddress((void**)&qph,  g_qh);
    cudaGetSymbolAddress((void**)&kph,  g_kh);
    cudaGetSymbolAddress((void**)&vph,  g_vh);
    cudaGetSymbolAddress((void**)&numh, g_numh);
    cudaGetSymbolAddress((void**)&denp, g_den);
    cudaGetSymbolAddress((void**)&mp,   g_m);
    cudaGetSymbolAddress((void**)&xqh,  g_xq_h);
    cudaGetSymbolAddress((void**)&xkvh, g_xkv_h);
    cudaGetSymbolAddress((void**)&atth, g_att_h);
    cudaGetSymbolAddress((void**)&wTh,  g_wT_h);

    cudaFuncSetAttribute(gemm_h, cudaFuncAttributeMaxDynamicSharedMemorySize, GEMM_SMEM);

    const int M = B_ * N0_;
    const float scale = 0.125f;

    mask_init<<<(B_ * N0_ + 255) / 256, 256>>>(kmask, mp, B_ * N0_);

    int n4 = M * D_ / 4;
    cvt_x<<<(n4 + 255) / 256, 256>>>(inputs_q,  xqh,  n4);
    cvt_x<<<(n4 + 255) / 256, 256>>>(inputs_kv, xkvh, n4);
    dim3 wtg(D_ / 32, D_ / 32, 4);
    cvt_wT<<<wtg, dim3(32, 8)>>>(Wq, Wk, Wv, Wo, wTh);

    dim3 gemmGrid(D_ / 128, M / 128);
    const size_t WSZ = (size_t)D_ * D_;
    gemm_h<<<gemmGrid, 256, GEMM_SMEM>>>(xqh,  wTh,           nullptr, qph, M, D_, D_, scale, bq, nullptr);
    gemm_h<<<gemmGrid, 256, GEMM_SMEM>>>(xkvh, wTh + WSZ,     nullptr, kph, M, D_, D_, 1.f, bk, nullptr);
    gemm_h<<<gemmGrid, 256, GEMM_SMEM>>>(xkvh, wTh + 2 * WSZ, nullptr, vph, M, D_, D_, 1.f, bv, kmask);

    // coarsen chain first (attention-independent)
    size_t toff = 0;
    int nl = N0_;
    for (int l = 0; l < LVLS - 1; l++) {
        int nl2 = nl / 2;
        size_t toff2 = toff + (size_t)B_ * nl;
        int tot2 = B_ * nl2 * (D_ / 2);
        coarsen_h<<<(tot2 + 255) / 256, 256>>>(qph + toff * D_, qph + toff2 * D_, nl2);
        coarsen_h<<<(tot2 + 255) / 256, 256>>>(kph + toff * D_, kph + toff2 * D_, nl2);
        coarsen_h<<<(tot2 + 255) / 256, 256>>>(vph + toff * D_, vph + toff2 * D_, nl2);
        int totm = B_ * nl2;
        coarsen_m<<<(totm + 255) / 256, 256>>>(mp + toff, mp + toff2, nl2);
        toff = toff2;
        nl = nl2;
    }

    // all 8 attention levels in ONE launch: grid.x = 256+128+...+2 = 510
    dim3 ag(510, H_, B_);
    hier_attn_all<<<ag, 128>>>(qph, kph, vph, mp, rpb, numh, denp);

    combine<<<B_ * N0_, 256>>>(numh, denp, qmask, atth);

    gemm_h<<<gemmGrid, 256, GEMM_SMEM>>>(atth, wTh + 3 * WSZ, out, nullptr, M, D_, D_, 1.f, bo, nullptr);
}

// round 15
// speedup vs baseline: 1.3403x; 1.0001x over previous
#include <cuda_runtime.h>
#include <cuda_fp16.h>
#include <math.h>
#include <stdint.h>

// ---------------- problem constants ----------------
#define B_   4
#define N0_  8192
#define D_   1024
#define H_   16
#define DH_  64
#define CB   32
#define LVLS 8
#define PYR_TOK 65280

// ---------------- device scratch ----------------
__device__ __half g_qh[(size_t)PYR_TOK * D_];
__device__ __half g_kh[(size_t)PYR_TOK * D_];
__device__ __half g_vh[(size_t)PYR_TOK * D_];
__device__ __half g_numh[(size_t)PYR_TOK * D_];
__device__ float  g_den[(size_t)PYR_TOK * H_];
__device__ float  g_m[PYR_TOK];
__device__ __half g_xq_h[(size_t)B_ * N0_ * D_];
__device__ __half g_xkv_h[(size_t)B_ * N0_ * D_];
__device__ __half g_att_h[(size_t)B_ * N0_ * D_];
__device__ __half g_wT_h[4 * (size_t)D_ * D_];

// ---------------- helpers ----------------
__device__ __forceinline__ uint32_t smem_cast(const void* p) {
    return (uint32_t)__cvta_generic_to_shared(p);
}
__device__ __forceinline__ void cpa16(uint32_t dst, const void* src) {
    asm volatile("cp.async.cg.shared.global [%0], [%1], 16;" :: "r"(dst), "l"(src));
}
#define CP_COMMIT() asm volatile("cp.async.commit_group;" ::: "memory")
#define CP_WAIT1()  asm volatile("cp.async.wait_group 1;" ::: "memory")
#define CP_WAIT0()  asm volatile("cp.async.wait_group 0;" ::: "memory")

__device__ __forceinline__ void ldsm4(uint32_t& r0, uint32_t& r1, uint32_t& r2, uint32_t& r3,
                                      uint32_t addr) {
    asm volatile("ldmatrix.sync.aligned.m8n8.x4.shared.b16 {%0,%1,%2,%3}, [%4];"
                 : "=r"(r0), "=r"(r1), "=r"(r2), "=r"(r3) : "r"(addr));
}
__device__ __forceinline__ void ldsm2t(uint32_t& r0, uint32_t& r1, uint32_t addr) {
    asm volatile("ldmatrix.sync.aligned.m8n8.x2.trans.shared.b16 {%0,%1}, [%2];"
                 : "=r"(r0), "=r"(r1) : "r"(addr));
}
__device__ __forceinline__ void mma_f16(float* c, const uint32_t* a, const uint32_t* b) {
    asm volatile(
        "mma.sync.aligned.m16n8k16.row.col.f32.f16.f16.f32 "
        "{%0,%1,%2,%3}, {%4,%5,%6,%7}, {%8,%9}, {%0,%1,%2,%3};"
        : "+f"(c[0]), "+f"(c[1]), "+f"(c[2]), "+f"(c[3])
        : "r"(a[0]), "r"(a[1]), "r"(a[2]), "r"(a[3]), "r"(b[0]), "r"(b[1]));
}

// ---------------- convert kernels ----------------
__global__ void cvt_x(const float* __restrict__ in, __half* __restrict__ out, int n4)
{
    int i = blockIdx.x * blockDim.x + threadIdx.x;
    if (i >= n4) return;
    float4 v = ((const float4*)in)[i];
    ((__half2*)out)[2 * i]     = __floats2half2_rn(v.x, v.y);
    ((__half2*)out)[2 * i + 1] = __floats2half2_rn(v.z, v.w);
}

__global__ void cvt_wT(const float* __restrict__ W0, const float* __restrict__ W1,
                       const float* __restrict__ W2, const float* __restrict__ W3,
                       __half* __restrict__ out)
{
    __shared__ float t[32][33];
    int z = blockIdx.z;
    const float* W = z == 0 ? W0 : z == 1 ? W1 : z == 2 ? W2 : W3;
    __half* o = out + (size_t)z * D_ * D_;
    int x0 = blockIdx.x * 32, y0 = blockIdx.y * 32;
    int tx = threadIdx.x, ty = threadIdx.y;
    #pragma unroll
    for (int i = 0; i < 4; i++)
        t[ty + i * 8][tx] = W[(size_t)(y0 + ty + i * 8) * D_ + x0 + tx];
    __syncthreads();
    #pragma unroll
    for (int i = 0; i < 4; i++)
        o[(size_t)(x0 + ty + i * 8) * D_ + y0 + tx] = __float2half(t[tx][ty + i * 8]);
}

// ---------------- fp16 GEMM (256 thr, 2 CTA/SM) ----------------
#define HSTR 72
#define HTILE (128 * HSTR)
#define GEMM_SMEM (4 * HTILE * 2)

__global__ __launch_bounds__(256, 2) void gemm_h(
    const __half* __restrict__ A, const __half* __restrict__ Bt,
    float* __restrict__ Co, __half* __restrict__ CoH,
    int M, int N, int K, float alpha,
    const float* __restrict__ bias, const int* __restrict__ rowmask)
{
    extern __shared__ __half smh[];
    __half* Abuf[2] = { smh,             smh + HTILE };
    __half* Bbuf[2] = { smh + 2 * HTILE, smh + 3 * HTILE };

    const int tid  = threadIdx.x;
    const int warp = tid >> 5;
    const int lane = tid & 31;
    const int wr   = warp >> 2;
    const int wc   = warp & 3;
    const int g    = lane >> 2;
    const int tig  = lane & 3;

    const int m0 = blockIdx.y * 128;
    const int n0 = blockIdx.x * 128;

    const int aRow = wr * 64 + ((lane >> 3) & 1) * 8 + (lane & 7);
    const int aCol = (lane >> 4) * 8;
    const int bRow = wc * 32 + (lane >> 4) * 8 + (lane & 7);
    const int bCol = ((lane >> 3) & 1) * 8;

    const uint32_t uA[2] = { smem_cast(Abuf[0]), smem_cast(Abuf[1]) };
    const uint32_t uB[2] = { smem_cast(Bbuf[0]), smem_cast(Bbuf[1]) };

    float acc[4][4][4];
    #pragma unroll
    for (int i = 0; i < 4; i++)
        #pragma unroll
        for (int j = 0; j < 4; j++)
            #pragma unroll
            for (int q = 0; q < 4; q++) acc[i][j][q] = 0.f;

    const int NIT = K / 64;

    auto load_tile = [&](int it, int s) {
        const int k0 = it * 64;
        #pragma unroll
        for (int i = 0; i < 4; i++) {
            int idx = tid + i * 256;
            int row = idx >> 3, c = idx & 7;
            uint32_t off = (uint32_t)(row * HSTR + c * 8) * 2;
            cpa16(uA[s] + off, A  + (size_t)(m0 + row) * K + k0 + c * 8);
            cpa16(uB[s] + off, Bt + (size_t)(n0 + row) * K + k0 + c * 8);
        }
        CP_COMMIT();
    };

    load_tile(0, 0);

    for (int it = 0; it < NIT; ++it) {
        const int s = it & 1;
        if (it + 1 < NIT) { load_tile(it + 1, s ^ 1); CP_WAIT1(); }
        else              { CP_WAIT0(); }
        __syncthreads();

        const uint32_t aB = uA[s] + (uint32_t)(aRow * HSTR + aCol) * 2;
        const uint32_t bB = uB[s] + (uint32_t)(bRow * HSTR + bCol) * 2;
        #pragma unroll
        for (int ks = 0; ks < 4; ks++) {
            uint32_t bfr[4][2];
            #pragma unroll
            for (int t = 0; t < 2; t++) {
                uint32_t r0, r1, r2, r3;
                ldsm4(r0, r1, r2, r3, bB + (uint32_t)(t * 16 * HSTR + ks * 16) * 2);
                bfr[2 * t][0] = r0; bfr[2 * t][1] = r1;
                bfr[2 * t + 1][0] = r2; bfr[2 * t + 1][1] = r3;
            }
            #pragma unroll
            for (int mf = 0; mf < 4; mf++) {
                uint32_t af[4];
                ldsm4(af[0], af[1], af[2], af[3],
                      aB + (uint32_t)(mf * 16 * HSTR + ks * 16) * 2);
                #pragma unroll
                for (int nf = 0; nf < 4; nf++)
                    mma_f16(acc[mf][nf], af, bfr[nf]);
            }
        }
        __syncthreads();
    }

    #pragma unroll
    for (int mf = 0; mf < 4; mf++) {
        int r0 = m0 + wr * 64 + mf * 16 + g;
        int r1 = r0 + 8;
        float mk0 = rowmask ? (float)rowmask[r0] : 1.f;
        float mk1 = rowmask ? (float)rowmask[r1] : 1.f;
        #pragma unroll
        for (int nf = 0; nf < 4; nf++) {
            int col = n0 + wc * 32 + nf * 8 + 2 * tig;
            float b0 = bias[col], b1 = bias[col + 1];
            float o00 = (acc[mf][nf][0] * alpha + b0) * mk0;
            float o01 = (acc[mf][nf][1] * alpha + b1) * mk0;
            float o10 = (acc[mf][nf][2] * alpha + b0) * mk1;
            float o11 = (acc[mf][nf][3] * alpha + b1) * mk1;
            if (CoH) {
                *(__half2*)(CoH + (size_t)r0 * N + col) = __floats2half2_rn(o00, o01);
                *(__half2*)(CoH + (size_t)r1 * N + col) = __floats2half2_rn(o10, o11);
            } else {
                *(float2*)(Co + (size_t)r0 * N + col) = make_float2(o00, o01);
                *(float2*)(Co + (size_t)r1 * N + col) = make_float2(o10, o11);
            }
        }
    }
}

// ---------------- mask init ----------------
__global__ void mask_init(const int* __restrict__ kmask, float* __restrict__ m0, int n)
{
    int i = blockIdx.x * blockDim.x + threadIdx.x;
    if (i < n) m0[i] = (float)kmask[i];
}

// ---------------- fused coarsen: z in {0,1,2} -> q/k/v (half2), z==3 -> mask ----
__global__ void coarsen_all(__half* __restrict__ qb, __half* __restrict__ kb,
                            __half* __restrict__ vb, float* __restrict__ mb,
                            size_t toff, size_t toff2, int nl2)
{
    const int z = blockIdx.z;
    int i = blockIdx.x * blockDim.x + threadIdx.x;
    if (z < 3) {
        const int cols2 = D_ / 2;
        int total = B_ * nl2 * cols2;
        if (i >= total) return;
        __half* arr = z == 0 ? qb : z == 1 ? kb : vb;
        const __half2* in = (const __half2*)(arr + toff * D_);
        __half2* out = (__half2*)(arr + toff2 * D_);
        int c2 = i % cols2;
        int n2 = (i / cols2) % nl2;
        int b  = i / (cols2 * nl2);
        size_t a = ((size_t)b * (2 * nl2) + 2 * n2) * cols2 + c2;
        float2 fa = __half22float2(in[a]);
        float2 fb = __half22float2(in[a + cols2]);
        out[i] = __floats2half2_rn(0.5f * (fa.x + fb.x), 0.5f * (fa.y + fb.y));
    } else {
        int total = B_ * nl2;
        if (i >= total) return;
        const float* in = mb + toff;
        float* out = mb + toff2;
        int n2 = i % nl2;
        int b  = i / nl2;
        size_t a = (size_t)b * (2 * nl2) + 2 * n2;
        out[i] = 0.5f * (in[a] + in[a + 1]);
    }
}

// ---------------- fused hierarchical attention: ALL levels in one launch ----------------
#define QSTR 72
#define KSTR 72
#define VSTR 72
#define PSTR 104

__global__ __launch_bounds__(128) void hier_attn_all(
    const __half* __restrict__ qP, const __half* __restrict__ kP, const __half* __restrict__ vP,
    const float* __restrict__ mP, const float* __restrict__ rpb,
    __half* __restrict__ numP, float* __restrict__ denP)
{
    __shared__ __half Qh[32 * QSTR];
    __shared__ __half Kh[96 * KSTR];
    __shared__ __half Vh[96 * VSTR];
    __shared__ __half Ph[32 * PSTR];
    __shared__ float srpb[128];
    __shared__ float smw[96];
    __shared__ float sden[32];

    int bx = blockIdx.x;
    int lvl = 0, nb = N0_ / CB;
    while (bx >= nb) { bx -= nb; nb >>= 1; lvl++; }
    const int blk = bx;
    const int nl = N0_ >> lvl;
    const size_t toff = (size_t)B_ * (2 * N0_ - 2 * (N0_ >> lvl));

    const __half* qL = qP + toff * D_;
    const __half* kL = kP + toff * D_;
    const __half* vL = vP + toff * D_;
    const float*  mL = mP + toff;
    const float*  rpbL = rpb + (size_t)lvl * H_ * (4 * CB - 1);
    __half* numL = numP + toff * D_;
    float*  denL = denP + toff * H_;

    const int h = blockIdx.y, b = blockIdx.z;
    const int tid = threadIdx.x;
    const int warp = tid >> 5;
    const int lane = tid & 31;
    const int g = lane >> 2, tig = lane & 3;
    const int mtile = warp >> 1;
    const int nh = warp & 1;

    const __half* qbase = qL + ((size_t)b * nl + (size_t)blk * CB) * D_ + h * DH_;
    for (int i = tid; i < 32 * 8; i += 128) {
        int qi = i >> 3, d8 = (i & 7) * 8;
        *(uint4*)&Qh[qi * QSTR + d8] = *(const uint4*)(qbase + (size_t)qi * D_ + d8);
    }
    const uint4 z4 = make_uint4(0, 0, 0, 0);
    for (int i = tid; i < 96 * 8; i += 128) {
        int p = i >> 3, d8 = (i & 7) * 8;
        int n = blk * CB + p - CB;
        uint4 kv = z4, vv = z4;
        if (n >= 0 && n < nl) {
            size_t off = ((size_t)b * nl + n) * D_ + h * DH_ + d8;
            kv = *(const uint4*)(kL + off);
            vv = *(const uint4*)(vL + off);
        }
        *(uint4*)&Kh[p * KSTR + d8] = kv;
        *(uint4*)&Vh[p * VSTR + d8] = vv;
    }
    for (int p = tid; p < 96; p += 128) {
        int n = blk * CB + p - CB;
        smw[p] = (n >= 0 && n < nl) ? mL[(size_t)b * nl + n] : 0.f;
    }
    for (int i = tid; i < 127; i += 128) srpb[i] = rpbL[h * 127 + i];
    if (tid < 32) sden[tid] = 0.f;
    __syncthreads();

    // phase 1: logits
    float c1[6][4];
    #pragma unroll
    for (int t = 0; t < 6; t++)
        #pragma unroll
        for (int q = 0; q < 4; q++) c1[t][q] = 0.f;

    const uint32_t qAddr = smem_cast(Qh) +
        (uint32_t)((mtile * 16 + ((lane >> 3) & 1) * 8 + (lane & 7)) * QSTR + (lane >> 4) * 8) * 2;
    const uint32_t kAddrBase = smem_cast(Kh);
    const int kRow = (lane >> 4) * 8 + (lane & 7);
    const int kColH = ((lane >> 3) & 1) * 8;

    #pragma unroll
    for (int ks = 0; ks < 4; ks++) {
        uint32_t a[4];
        ldsm4(a[0], a[1], a[2], a[3], qAddr + (uint32_t)(ks * 16) * 2);
        #pragma unroll
        for (int t = 0; t < 3; t++) {
            int prow = nh * 48 + t * 16 + kRow;
            uint32_t r0, r1, r2, r3;
            ldsm4(r0, r1, r2, r3,
                  kAddrBase + (uint32_t)(prow * KSTR + kColH + ks * 16) * 2);
            uint32_t b0[2] = { r0, r1 }, b1[2] = { r2, r3 };
            mma_f16(c1[2 * t],     a, b0);
            mma_f16(c1[2 * t + 1], a, b1);
        }
    }

    // epilogue -> P, den
    {
        const int row0 = mtile * 16 + g;
        const int row1 = row0 + 8;
        float rs0 = 0.f, rs1 = 0.f;
        #pragma unroll
        for (int t = 0; t < 6; t++) {
            int p0 = nh * 48 + (t >> 1) * 16 + (t & 1) * 8 + 2 * tig;
            #pragma unroll
            for (int half = 0; half < 2; half++) {
                int row = half ? row1 : row0;
                float w0, w1;
                #pragma unroll
                for (int j = 0; j < 2; j++) {
                    int p = p0 + j;
                    float lg = c1[t][half * 2 + j] + srpb[p - row + CB - 1];
                    float valid = 1.f;
                    if (lvl > 0) {
                        int bk3 = p >> 5, pl = p & 31;
                        bool inv = (bk3 == 1) ||
                                   (bk3 == 0 && row < 16 && pl >= 16) ||
                                   (bk3 == 2 && row >= 16 && pl < 16);
                        valid = inv ? 0.f : 1.f;
                    }
                    float w = expf(lg) * valid * smw[p];
                    __half wh = __float2half_rn(w);
                    float wr = __half2float(wh);
                    if (j == 0) w0 = wr; else w1 = wr;
                }
                *(__half2*)&Ph[row * PSTR + p0] = __floats2half2_rn(w0, w1);
                if (half) rs1 += w0 + w1; else rs0 += w0 + w1;
            }
        }
        rs0 += __shfl_xor_sync(0xFFFFFFFF, rs0, 1);
        rs0 += __shfl_xor_sync(0xFFFFFFFF, rs0, 2);
        rs1 += __shfl_xor_sync(0xFFFFFFFF, rs1, 1);
        rs1 += __shfl_xor_sync(0xFFFFFFFF, rs1, 2);
        if (tig == 0) {
            atomicAdd(&sden[row0], rs0);
            atomicAdd(&sden[row1], rs1);
        }
    }
    __syncthreads();

    if (tid < 32)
        denL[((size_t)b * nl + blk * CB + tid) * H_ + h] = sden[tid];

    // phase 2: num = P @ V
    float c2[4][4];
    #pragma unroll
    for (int t = 0; t < 4; t++)
        #pragma unroll
        for (int q = 0; q < 4; q++) c2[t][q] = 0.f;

    const uint32_t pAddr = smem_cast(Ph) +
        (uint32_t)((mtile * 16 + ((lane >> 3) & 1) * 8 + (lane & 7)) * PSTR + (lane >> 4) * 8) * 2;
    const uint32_t vAddrBase = smem_cast(Vh);
    const int dhalf = nh * 32;

    #pragma unroll
    for (int ks = 0; ks < 6; ks++) {
        uint32_t a[4];
        ldsm4(a[0], a[1], a[2], a[3], pAddr + (uint32_t)(ks * 16) * 2);
        #pragma unroll
        for (int t = 0; t < 4; t++) {
            uint32_t b[2];
            ldsm2t(b[0], b[1],
                   vAddrBase + (uint32_t)((ks * 16 + (lane & 15)) * VSTR + dhalf + t * 8) * 2);
            mma_f16(c2[t], a, b);
        }
    }

    // write num (fp16)
    {
        int row0 = blk * CB + mtile * 16 + g;
        __half* base = numL + ((size_t)b * nl + row0) * D_ + h * DH_;
        #pragma unroll
        for (int t = 0; t < 4; t++) {
            int col = dhalf + t * 8 + 2 * tig;
            *(__half2*)(base + col)          = __floats2half2_rn(c2[t][0], c2[t][1]);
            *(__half2*)(base + 8 * D_ + col) = __floats2half2_rn(c2[t][2], c2[t][3]);
        }
    }
}

// ---------------- combine: block per (b,n) row ----------------
__global__ __launch_bounds__(256) void combine(
    const __half* __restrict__ num, const float* __restrict__ den,
    const int* __restrict__ qmask, __half* __restrict__ att)
{
    __shared__ float dinv[16];
    __shared__ float sq;
    const int bn = blockIdx.x;
    const int b = bn >> 13;
    const int n = bn & (N0_ - 1);
    const int tid = threadIdx.x;

    if (tid < 16) {
        float s = 0.f;
        size_t toff = 0;
        #pragma unroll
        for (int l = 0; l < LVLS; l++) {
            int nl = N0_ >> l;
            s += den[(toff + (size_t)b * nl + (n >> l)) * H_ + tid];
            toff += (size_t)B_ * nl;
        }
        dinv[tid] = 1.f / (s + 1e-9f);
    }
    if (tid == 0) sq = (float)qmask[bn];
    __syncthreads();

    const int e0 = tid * 4;
    const int h = e0 >> 6;
    float a0 = 0.f, a1 = 0.f, a2 = 0.f, a3 = 0.f;
    size_t toff = 0;
    #pragma unroll
    for (int l = 0; l < LVLS; l++) {
        int nl = N0_ >> l;
        size_t tk = toff + (size_t)b * nl + (n >> l);
        uint2 u = *(const uint2*)(num + tk * D_ + e0);
        float2 f0 = __half22float2(*(__half2*)&u.x);
        float2 f1 = __half22float2(*(__half2*)&u.y);
        a0 += f0.x; a1 += f0.y; a2 += f1.x; a3 += f1.y;
        toff += (size_t)B_ * nl;
    }
    float s = dinv[h] * sq;
    __half2 o0 = __floats2half2_rn(a0 * s, a1 * s);
    __half2 o1 = __floats2half2_rn(a2 * s, a3 * s);
    *(uint2*)(att + (size_t)bn * D_ + e0) =
        make_uint2(*(uint32_t*)&o0, *(uint32_t*)&o1);
}

// ---------------- host launch ----------------
extern "C" void kernel_launch(void* const* d_in, const int* in_sizes, int n_in,
                              void* d_out, int out_size)
{
    const float* inputs_q  = (const float*)d_in[0];
    const float* inputs_kv = (const float*)d_in[1];
    const int*   qmask     = (const int*)d_in[2];
    const int*   kmask     = (const int*)d_in[3];
    const float* Wq        = (const float*)d_in[4];
    const float* bq        = (const float*)d_in[5];
    const float* Wk        = (const float*)d_in[6];
    const float* bk        = (const float*)d_in[7];
    const float* Wv        = (const float*)d_in[8];
    const float* bv        = (const float*)d_in[9];
    const float* Wo        = (const float*)d_in[10];
    const float* bo        = (const float*)d_in[11];
    const float* rpb       = (const float*)d_in[12];
    float* out             = (float*)d_out;

    float *denp, *mp;
    __half *qph, *kph, *vph, *numh, *xqh, *xkvh, *atth, *wTh;
    cudaGetSymbolAddress((void**)&qph,  g_qh);
    cudaGetSymbolAddress((void**)&kph,  g_kh);
    cudaGetSymbolAddress((void**)&vph,  g_vh);
    cudaGetSymbolAddress((void**)&numh, g_numh);
    cudaGetSymbolAddress((void**)&denp, g_den);
    cudaGetSymbolAddress((void**)&mp,   g_m);
    cudaGetSymbolAddress((void**)&xqh,  g_xq_h);
    cudaGetSymbolAddress((void**)&xkvh, g_xkv_h);
    cudaGetSymbolAddress((void**)&atth, g_att_h);
    cudaGetSymbolAddress((void**)&wTh,  g_wT_h);

    cudaFuncSetAttribute(gemm_h, cudaFuncAttributeMaxDynamicSharedMemorySize, GEMM_SMEM);

    const int M = B_ * N0_;
    const float scale = 0.125f;

    mask_init<<<(B_ * N0_ + 255) / 256, 256>>>(kmask, mp, B_ * N0_);

    int n4 = M * D_ / 4;
    cvt_x<<<(n4 + 255) / 256, 256>>>(inputs_q,  xqh,  n4);
    cvt_x<<<(n4 + 255) / 256, 256>>>(inputs_kv, xkvh, n4);
    dim3 wtg(D_ / 32, D_ / 32, 4);
    cvt_wT<<<wtg, dim3(32, 8)>>>(Wq, Wk, Wv, Wo, wTh);

    dim3 gemmGrid(D_ / 128, M / 128);
    const size_t WSZ = (size_t)D_ * D_;
    gemm_h<<<gemmGrid, 256, GEMM_SMEM>>>(xqh,  wTh,           nullptr, qph, M, D_, D_, scale, bq, nullptr);
    gemm_h<<<gemmGrid, 256, GEMM_SMEM>>>(xkvh, wTh + WSZ,     nullptr, kph, M, D_, D_, 1.f, bk, nullptr);
    gemm_h<<<gemmGrid, 256, GEMM_SMEM>>>(xkvh, wTh + 2 * WSZ, nullptr, vph, M, D_, D_, 1.f, bv, kmask);

    // coarsen chain: ONE launch per level (q/k/v/mask via grid.z)
    size_t toff = 0;
    int nl = N0_;
    for (int l = 0; l < LVLS - 1; l++) {
        int nl2 = nl / 2;
        size_t toff2 = toff + (size_t)B_ * nl;
        int tot2 = B_ * nl2 * (D_ / 2);
        dim3 cg((tot2 + 255) / 256, 1, 4);
        coarsen_all<<<cg, 256>>>(qph, kph, vph, mp, toff, toff2, nl2);
        toff = toff2;
        nl = nl2;
    }

    // all 8 attention levels in ONE launch
    dim3 ag(510, H_, B_);
    hier_attn_all<<<ag, 128>>>(qph, kph, vph, mp, rpb, numh, denp);

    combine<<<B_ * N0_, 256>>>(numh, denp, qmask, atth);

    gemm_h<<<gemmGrid, 256, GEMM_SMEM>>>(atth, wTh + 3 * WSZ, out, nullptr, M, D_, D_, 1.f, bo, nullptr);
}

// round 16
// speedup vs baseline: 1.4887x; 1.1107x over previous
#include <cuda_runtime.h>
#include <cuda_fp16.h>
#include <math.h>
#include <stdint.h>

// ---------------- problem constants ----------------
#define B_   4
#define N0_  8192
#define D_   1024
#define H_   16
#define DH_  64
#define CB   32
#define LVLS 8
#define PYR_TOK 65280

// ---------------- device scratch ----------------
__device__ __half g_qh[(size_t)PYR_TOK * D_];
__device__ __half g_kh[(size_t)PYR_TOK * D_];
__device__ __half g_vh[(size_t)PYR_TOK * D_];
__device__ __half g_numh[(size_t)PYR_TOK * D_];
__device__ float  g_den[(size_t)PYR_TOK * H_];
__device__ float  g_m[PYR_TOK];
__device__ __half g_xq_h[(size_t)B_ * N0_ * D_];
__device__ __half g_xkv_h[(size_t)B_ * N0_ * D_];
__device__ __half g_att_h[(size_t)B_ * N0_ * D_];
__device__ __half g_wT_h[4 * (size_t)D_ * D_];

// ---------------- helpers ----------------
__device__ __forceinline__ uint32_t smem_cast(const void* p) {
    return (uint32_t)__cvta_generic_to_shared(p);
}
__device__ __forceinline__ void cpa16(uint32_t dst, const void* src) {
    asm volatile("cp.async.cg.shared.global [%0], [%1], 16;" :: "r"(dst), "l"(src));
}
#define CP_COMMIT() asm volatile("cp.async.commit_group;" ::: "memory")
#define CP_WAIT1()  asm volatile("cp.async.wait_group 1;" ::: "memory")
#define CP_WAIT0()  asm volatile("cp.async.wait_group 0;" ::: "memory")

__device__ __forceinline__ void ldsm4(uint32_t& r0, uint32_t& r1, uint32_t& r2, uint32_t& r3,
                                      uint32_t addr) {
    asm volatile("ldmatrix.sync.aligned.m8n8.x4.shared.b16 {%0,%1,%2,%3}, [%4];"
                 : "=r"(r0), "=r"(r1), "=r"(r2), "=r"(r3) : "r"(addr));
}
__device__ __forceinline__ void ldsm2t(uint32_t& r0, uint32_t& r1, uint32_t addr) {
    asm volatile("ldmatrix.sync.aligned.m8n8.x2.trans.shared.b16 {%0,%1}, [%2];"
                 : "=r"(r0), "=r"(r1) : "r"(addr));
}
__device__ __forceinline__ void mma_f16(float* c, const uint32_t* a, const uint32_t* b) {
    asm volatile(
        "mma.sync.aligned.m16n8k16.row.col.f32.f16.f16.f32 "
        "{%0,%1,%2,%3}, {%4,%5,%6,%7}, {%8,%9}, {%0,%1,%2,%3};"
        : "+f"(c[0]), "+f"(c[1]), "+f"(c[2]), "+f"(c[3])
        : "r"(a[0]), "r"(a[1]), "r"(a[2]), "r"(a[3]), "r"(b[0]), "r"(b[1]));
}

// ---------------- convert kernels ----------------
__global__ void cvt_x(const float* __restrict__ in, __half* __restrict__ out, int n4)
{
    int i = blockIdx.x * blockDim.x + threadIdx.x;
    if (i >= n4) return;
    float4 v = ((const float4*)in)[i];
    ((__half2*)out)[2 * i]     = __floats2half2_rn(v.x, v.y);
    ((__half2*)out)[2 * i + 1] = __floats2half2_rn(v.z, v.w);
}

__global__ void cvt_wT(const float* __restrict__ W0, const float* __restrict__ W1,
                       const float* __restrict__ W2, const float* __restrict__ W3,
                       __half* __restrict__ out)
{
    __shared__ float t[32][33];
    int z = blockIdx.z;
    const float* W = z == 0 ? W0 : z == 1 ? W1 : z == 2 ? W2 : W3;
    __half* o = out + (size_t)z * D_ * D_;
    int x0 = blockIdx.x * 32, y0 = blockIdx.y * 32;
    int tx = threadIdx.x, ty = threadIdx.y;
    #pragma unroll
    for (int i = 0; i < 4; i++)
        t[ty + i * 8][tx] = W[(size_t)(y0 + ty + i * 8) * D_ + x0 + tx];
    __syncthreads();
    #pragma unroll
    for (int i = 0; i < 4; i++)
        o[(size_t)(x0 + ty + i * 8) * D_ + y0 + tx] = __float2half(t[tx][ty + i * 8]);
}

// ---------------- fp16 GEMM (256 thr, 2 CTA/SM) ----------------
#define HSTR 72
#define HTILE (128 * HSTR)
#define GEMM_SMEM (4 * HTILE * 2)

__global__ __launch_bounds__(256, 2) void gemm_h(
    const __half* __restrict__ A, const __half* __restrict__ Bt,
    float* __restrict__ Co, __half* __restrict__ CoH,
    int M, int N, int K, float alpha,
    const float* __restrict__ bias, const int* __restrict__ rowmask)
{
    extern __shared__ __half smh[];
    __half* Abuf[2] = { smh,             smh + HTILE };
    __half* Bbuf[2] = { smh + 2 * HTILE, smh + 3 * HTILE };

    const int tid  = threadIdx.x;
    const int warp = tid >> 5;
    const int lane = tid & 31;
    const int wr   = warp >> 2;
    const int wc   = warp & 3;
    const int g    = lane >> 2;
    const int tig  = lane & 3;

    const int m0 = blockIdx.y * 128;
    const int n0 = blockIdx.x * 128;

    const int aRow = wr * 64 + ((lane >> 3) & 1) * 8 + (lane & 7);
    const int aCol = (lane >> 4) * 8;
    const int bRow = wc * 32 + (lane >> 4) * 8 + (lane & 7);
    const int bCol = ((lane >> 3) & 1) * 8;

    const uint32_t uA[2] = { smem_cast(Abuf[0]), smem_cast(Abuf[1]) };
    const uint32_t uB[2] = { smem_cast(Bbuf[0]), smem_cast(Bbuf[1]) };

    float acc[4][4][4];
    #pragma unroll
    for (int i = 0; i < 4; i++)
        #pragma unroll
        for (int j = 0; j < 4; j++)
            #pragma unroll
            for (int q = 0; q < 4; q++) acc[i][j][q] = 0.f;

    const int NIT = K / 64;

    auto load_tile = [&](int it, int s) {
        const int k0 = it * 64;
        #pragma unroll
        for (int i = 0; i < 4; i++) {
            int idx = tid + i * 256;
            int row = idx >> 3, c = idx & 7;
            uint32_t off = (uint32_t)(row * HSTR + c * 8) * 2;
            cpa16(uA[s] + off, A  + (size_t)(m0 + row) * K + k0 + c * 8);
            cpa16(uB[s] + off, Bt + (size_t)(n0 + row) * K + k0 + c * 8);
        }
        CP_COMMIT();
    };

    load_tile(0, 0);

    for (int it = 0; it < NIT; ++it) {
        const int s = it & 1;
        if (it + 1 < NIT) { load_tile(it + 1, s ^ 1); CP_WAIT1(); }
        else              { CP_WAIT0(); }
        __syncthreads();

        const uint32_t aB = uA[s] + (uint32_t)(aRow * HSTR + aCol) * 2;
        const uint32_t bB = uB[s] + (uint32_t)(bRow * HSTR + bCol) * 2;
        #pragma unroll
        for (int ks = 0; ks < 4; ks++) {
            uint32_t bfr[4][2];
            #pragma unroll
            for (int t = 0; t < 2; t++) {
                uint32_t r0, r1, r2, r3;
                ldsm4(r0, r1, r2, r3, bB + (uint32_t)(t * 16 * HSTR + ks * 16) * 2);
                bfr[2 * t][0] = r0; bfr[2 * t][1] = r1;
                bfr[2 * t + 1][0] = r2; bfr[2 * t + 1][1] = r3;
            }
            #pragma unroll
            for (int mf = 0; mf < 4; mf++) {
                uint32_t af[4];
                ldsm4(af[0], af[1], af[2], af[3],
                      aB + (uint32_t)(mf * 16 * HSTR + ks * 16) * 2);
                #pragma unroll
                for (int nf = 0; nf < 4; nf++)
                    mma_f16(acc[mf][nf], af, bfr[nf]);
            }
        }
        __syncthreads();
    }

    #pragma unroll
    for (int mf = 0; mf < 4; mf++) {
        int r0 = m0 + wr * 64 + mf * 16 + g;
        int r1 = r0 + 8;
        float mk0 = rowmask ? (float)rowmask[r0] : 1.f;
        float mk1 = rowmask ? (float)rowmask[r1] : 1.f;
        #pragma unroll
        for (int nf = 0; nf < 4; nf++) {
            int col = n0 + wc * 32 + nf * 8 + 2 * tig;
            float b0 = bias[col], b1 = bias[col + 1];
            float o00 = (acc[mf][nf][0] * alpha + b0) * mk0;
            float o01 = (acc[mf][nf][1] * alpha + b1) * mk0;
            float o10 = (acc[mf][nf][2] * alpha + b0) * mk1;
            float o11 = (acc[mf][nf][3] * alpha + b1) * mk1;
            if (CoH) {
                *(__half2*)(CoH + (size_t)r0 * N + col) = __floats2half2_rn(o00, o01);
                *(__half2*)(CoH + (size_t)r1 * N + col) = __floats2half2_rn(o10, o11);
            } else {
                *(float2*)(Co + (size_t)r0 * N + col) = make_float2(o00, o01);
                *(float2*)(Co + (size_t)r1 * N + col) = make_float2(o10, o11);
            }
        }
    }
}

// ---------------- mask init ----------------
__global__ void mask_init(const int* __restrict__ kmask, float* __restrict__ m0, int n)
{
    int i = blockIdx.x * blockDim.x + threadIdx.x;
    if (i < n) m0[i] = (float)kmask[i];
}

// ---------------- one-pass pyramid coarsen (q/k/v) ----------------
// grid (16, 64, 12): x = d-chunk (64 halves), y = segment (128 level-0 tokens), z = which*4+b
// Each block builds levels 1..7 of its segment/chunk via smem tree, rounding to fp16
// at each level exactly like the pairwise chain.
__global__ __launch_bounds__(256) void coarsen_tree(
    __half* __restrict__ qb, __half* __restrict__ kb, __half* __restrict__ vb)
{
    __shared__ __half2 S[192 * 32];
    const int chunk = blockIdx.x;
    const int seg   = blockIdx.y;
    const int zz    = blockIdx.z;
    const int b     = zz & 3;
    const int which = zz >> 2;
    __half* arr = which == 0 ? qb : which == 1 ? kb : vb;

    const int tid  = threadIdx.x;
    const int c2   = tid & 31;
    const int trow = tid >> 5;

    const int D2 = D_ / 2;
    const __half2* gin = (const __half2*)arr;
    __half2* gout = (__half2*)arr;

    // load 128 level-0 tokens (warp = one token row, contiguous 128B)
    size_t base0 = ((size_t)b * N0_ + (size_t)seg * 128) * D2 + chunk * 32;
    #pragma unroll
    for (int it = 0; it < 16; it++) {
        int tok = it * 8 + trow;
        S[tok * 32 + c2] = gin[base0 + (size_t)tok * D2 + c2];
    }
    __syncthreads();

    int src = 0, dst = 128;
    int nt = 128;
    size_t toff = 0;
    #pragma unroll
    for (int l = 1; l < LVLS; l++) {
        nt >>= 1;
        toff += (size_t)B_ * (N0_ >> (l - 1));
        const int nl = N0_ >> l;
        size_t gbase = (toff + (size_t)b * nl + (size_t)seg * nt) * D2 + chunk * 32;
        for (int it = 0; it < (nt + 7) / 8; it++) {
            int j = it * 8 + trow;
            if (j < nt) {
                float2 fa = __half22float2(S[(src + 2 * j)     * 32 + c2]);
                float2 fb = __half22float2(S[(src + 2 * j + 1) * 32 + c2]);
                __half2 r = __floats2half2_rn(0.5f * (fa.x + fb.x), 0.5f * (fa.y + fb.y));
                S[(dst + j) * 32 + c2] = r;
                gout[gbase + (size_t)j * D2 + c2] = r;
            }
        }
        __syncthreads();
        int t = src; src = dst; dst = t;
    }
}

// ---------------- one-pass pyramid coarsen (mask, fp32) ----------------
// grid (64, B_), 128 threads
__global__ void coarsen_mask_tree(float* __restrict__ mb)
{
    __shared__ float S[192];
    const int seg = blockIdx.x;
    const int b   = blockIdx.y;
    const int tid = threadIdx.x;

    S[tid] = mb[(size_t)b * N0_ + (size_t)seg * 128 + tid];
    __syncthreads();

    int src = 0, dst = 128;
    int nt = 128;
    size_t toff = 0;
    #pragma unroll
    for (int l = 1; l < LVLS; l++) {
        nt >>= 1;
        toff += (size_t)B_ * (N0_ >> (l - 1));
        const int nl = N0_ >> l;
        if (tid < nt) {
            float r = 0.5f * (S[src + 2 * tid] + S[src + 2 * tid + 1]);
            S[dst + tid] = r;
            mb[toff + (size_t)b * nl + (size_t)seg * nt + tid] = r;
        }
        __syncthreads();
        int t = src; src = dst; dst = t;
    }
}

// ---------------- fused hierarchical attention: ALL levels in one launch ----------------
#define QSTR 72
#define KSTR 72
#define VSTR 72
#define PSTR 104

__global__ __launch_bounds__(128) void hier_attn_all(
    const __half* __restrict__ qP, const __half* __restrict__ kP, const __half* __restrict__ vP,
    const float* __restrict__ mP, const float* __restrict__ rpb,
    __half* __restrict__ numP, float* __restrict__ denP)
{
    __shared__ __half Qh[32 * QSTR];
    __shared__ __half Kh[96 * KSTR];
    __shared__ __half Vh[96 * VSTR];
    __shared__ __half Ph[32 * PSTR];
    __shared__ float srpb[128];
    __shared__ float smw[96];
    __shared__ float sden[32];

    int bx = blockIdx.x;
    int lvl = 0, nb = N0_ / CB;
    while (bx >= nb) { bx -= nb; nb >>= 1; lvl++; }
    const int blk = bx;
    const int nl = N0_ >> lvl;
    const size_t toff = (size_t)B_ * (2 * N0_ - 2 * (N0_ >> lvl));

    const __half* qL = qP + toff * D_;
    const __half* kL = kP + toff * D_;
    const __half* vL = vP + toff * D_;
    const float*  mL = mP + toff;
    const float*  rpbL = rpb + (size_t)lvl * H_ * (4 * CB - 1);
    __half* numL = numP + toff * D_;
    float*  denL = denP + toff * H_;

    const int h = blockIdx.y, b = blockIdx.z;
    const int tid = threadIdx.x;
    const int warp = tid >> 5;
    const int lane = tid & 31;
    const int g = lane >> 2, tig = lane & 3;
    const int mtile = warp >> 1;
    const int nh = warp & 1;

    const __half* qbase = qL + ((size_t)b * nl + (size_t)blk * CB) * D_ + h * DH_;
    for (int i = tid; i < 32 * 8; i += 128) {
        int qi = i >> 3, d8 = (i & 7) * 8;
        *(uint4*)&Qh[qi * QSTR + d8] = *(const uint4*)(qbase + (size_t)qi * D_ + d8);
    }
    const uint4 z4 = make_uint4(0, 0, 0, 0);
    for (int i = tid; i < 96 * 8; i += 128) {
        int p = i >> 3, d8 = (i & 7) * 8;
        int n = blk * CB + p - CB;
        uint4 kv = z4, vv = z4;
        if (n >= 0 && n < nl) {
            size_t off = ((size_t)b * nl + n) * D_ + h * DH_ + d8;
            kv = *(const uint4*)(kL + off);
            vv = *(const uint4*)(vL + off);
        }
        *(uint4*)&Kh[p * KSTR + d8] = kv;
        *(uint4*)&Vh[p * VSTR + d8] = vv;
    }
    for (int p = tid; p < 96; p += 128) {
        int n = blk * CB + p - CB;
        smw[p] = (n >= 0 && n < nl) ? mL[(size_t)b * nl + n] : 0.f;
    }
    for (int i = tid; i < 127; i += 128) srpb[i] = rpbL[h * 127 + i];
    if (tid < 32) sden[tid] = 0.f;
    __syncthreads();

    // phase 1: logits
    float c1[6][4];
    #pragma unroll
    for (int t = 0; t < 6; t++)
        #pragma unroll
        for (int q = 0; q < 4; q++) c1[t][q] = 0.f;

    const uint32_t qAddr = smem_cast(Qh) +
        (uint32_t)((mtile * 16 + ((lane >> 3) & 1) * 8 + (lane & 7)) * QSTR + (lane >> 4) * 8) * 2;
    const uint32_t kAddrBase = smem_cast(Kh);
    const int kRow = (lane >> 4) * 8 + (lane & 7);
    const int kColH = ((lane >> 3) & 1) * 8;

    #pragma unroll
    for (int ks = 0; ks < 4; ks++) {
        uint32_t a[4];
        ldsm4(a[0], a[1], a[2], a[3], qAddr + (uint32_t)(ks * 16) * 2);
        #pragma unroll
        for (int t = 0; t < 3; t++) {
            int prow = nh * 48 + t * 16 + kRow;
            uint32_t r0, r1, r2, r3;
            ldsm4(r0, r1, r2, r3,
                  kAddrBase + (uint32_t)(prow * KSTR + kColH + ks * 16) * 2);
            uint32_t b0[2] = { r0, r1 }, b1[2] = { r2, r3 };
            mma_f16(c1[2 * t],     a, b0);
            mma_f16(c1[2 * t + 1], a, b1);
        }
    }

    // epilogue -> P, den
    {
        const int row0 = mtile * 16 + g;
        const int row1 = row0 + 8;
        float rs0 = 0.f, rs1 = 0.f;
        #pragma unroll
        for (int t = 0; t < 6; t++) {
            int p0 = nh * 48 + (t >> 1) * 16 + (t & 1) * 8 + 2 * tig;
            #pragma unroll
            for (int half = 0; half < 2; half++) {
                int row = half ? row1 : row0;
                float w0, w1;
                #pragma unroll
                for (int j = 0; j < 2; j++) {
                    int p = p0 + j;
                    float lg = c1[t][half * 2 + j] + srpb[p - row + CB - 1];
                    float valid = 1.f;
                    if (lvl > 0) {
                        int bk3 = p >> 5, pl = p & 31;
                        bool inv = (bk3 == 1) ||
                                   (bk3 == 0 && row < 16 && pl >= 16) ||
                                   (bk3 == 2 && row >= 16 && pl < 16);
                        valid = inv ? 0.f : 1.f;
                    }
                    float w = expf(lg) * valid * smw[p];
                    __half wh = __float2half_rn(w);
                    float wr = __half2float(wh);
                    if (j == 0) w0 = wr; else w1 = wr;
                }
                *(__half2*)&Ph[row * PSTR + p0] = __floats2half2_rn(w0, w1);
                if (half) rs1 += w0 + w1; else rs0 += w0 + w1;
            }
        }
        rs0 += __shfl_xor_sync(0xFFFFFFFF, rs0, 1);
        rs0 += __shfl_xor_sync(0xFFFFFFFF, rs0, 2);
        rs1 += __shfl_xor_sync(0xFFFFFFFF, rs1, 1);
        rs1 += __shfl_xor_sync(0xFFFFFFFF, rs1, 2);
        if (tig == 0) {
            atomicAdd(&sden[row0], rs0);
            atomicAdd(&sden[row1], rs1);
        }
    }
    __syncthreads();

    if (tid < 32)
        denL[((size_t)b * nl + blk * CB + tid) * H_ + h] = sden[tid];

    // phase 2: num = P @ V
    float c2[4][4];
    #pragma unroll
    for (int t = 0; t < 4; t++)
        #pragma unroll
        for (int q = 0; q < 4; q++) c2[t][q] = 0.f;

    const uint32_t pAddr = smem_cast(Ph) +
        (uint32_t)((mtile * 16 + ((lane >> 3) & 1) * 8 + (lane & 7)) * PSTR + (lane >> 4) * 8) * 2;
    const uint32_t vAddrBase = smem_cast(Vh);
    const int dhalf = nh * 32;

    #pragma unroll
    for (int ks = 0; ks < 6; ks++) {
        uint32_t a[4];
        ldsm4(a[0], a[1], a[2], a[3], pAddr + (uint32_t)(ks * 16) * 2);
        #pragma unroll
        for (int t = 0; t < 4; t++) {
            uint32_t b[2];
            ldsm2t(b[0], b[1],
                   vAddrBase + (uint32_t)((ks * 16 + (lane & 15)) * VSTR + dhalf + t * 8) * 2);
            mma_f16(c2[t], a, b);
        }
    }

    // write num (fp16)
    {
        int row0 = blk * CB + mtile * 16 + g;
        __half* base = numL + ((size_t)b * nl + row0) * D_ + h * DH_;
        #pragma unroll
        for (int t = 0; t < 4; t++) {
            int col = dhalf + t * 8 + 2 * tig;
            *(__half2*)(base + col)          = __floats2half2_rn(c2[t][0], c2[t][1]);
            *(__half2*)(base + 8 * D_ + col) = __floats2half2_rn(c2[t][2], c2[t][3]);
        }
    }
}

// ---------------- combine: block per (b,n) row ----------------
__global__ __launch_bounds__(256) void combine(
    const __half* __restrict__ num, const float* __restrict__ den,
    const int* __restrict__ qmask, __half* __restrict__ att)
{
    __shared__ float dinv[16];
    __shared__ float sq;
    const int bn = blockIdx.x;
    const int b = bn >> 13;
    const int n = bn & (N0_ - 1);
    const int tid = threadIdx.x;

    if (tid < 16) {
        float s = 0.f;
        size_t toff = 0;
        #pragma unroll
        for (int l = 0; l < LVLS; l++) {
            int nl = N0_ >> l;
            s += den[(toff + (size_t)b * nl + (n >> l)) * H_ + tid];
            toff += (size_t)B_ * nl;
        }
        dinv[tid] = 1.f / (s + 1e-9f);
    }
    if (tid == 0) sq = (float)qmask[bn];
    __syncthreads();

    const int e0 = tid * 4;
    const int h = e0 >> 6;
    float a0 = 0.f, a1 = 0.f, a2 = 0.f, a3 = 0.f;
    size_t toff = 0;
    #pragma unroll
    for (int l = 0; l < LVLS; l++) {
        int nl = N0_ >> l;
        size_t tk = toff + (size_t)b * nl + (n >> l);
        uint2 u = *(const uint2*)(num + tk * D_ + e0);
        float2 f0 = __half22float2(*(__half2*)&u.x);
        float2 f1 = __half22float2(*(__half2*)&u.y);
        a0 += f0.x; a1 += f0.y; a2 += f1.x; a3 += f1.y;
        toff += (size_t)B_ * nl;
    }
    float s = dinv[h] * sq;
    __half2 o0 = __floats2half2_rn(a0 * s, a1 * s);
    __half2 o1 = __floats2half2_rn(a2 * s, a3 * s);
    *(uint2*)(att + (size_t)bn * D_ + e0) =
        make_uint2(*(uint32_t*)&o0, *(uint32_t*)&o1);
}

// ---------------- host launch ----------------
extern "C" void kernel_launch(void* const* d_in, const int* in_sizes, int n_in,
                              void* d_out, int out_size)
{
    const float* inputs_q  = (const float*)d_in[0];
    const float* inputs_kv = (const float*)d_in[1];
    const int*   qmask     = (const int*)d_in[2];
    const int*   kmask     = (const int*)d_in[3];
    const float* Wq        = (const float*)d_in[4];
    const float* bq        = (const float*)d_in[5];
    const float* Wk        = (const float*)d_in[6];
    const float* bk        = (const float*)d_in[7];
    const float* Wv        = (const float*)d_in[8];
    const float* bv        = (const float*)d_in[9];
    const float* Wo        = (const float*)d_in[10];
    const float* bo        = (const float*)d_in[11];
    const float* rpb       = (const float*)d_in[12];
    float* out             = (float*)d_out;

    float *denp, *mp;
    __half *qph, *kph, *vph, *numh, *xqh, *xkvh, *atth, *wTh;
    cudaGetSymbolAddress((void**)&qph,  g_qh);
    cudaGetSymbolAddress((void**)&kph,  g_kh);
    cudaGetSymbolAddress((void**)&vph,  g_vh);
    cudaGetSymbolAddress((void**)&numh, g_numh);
    cudaGetSymbolAddress((void**)&denp, g_den);
    cudaGetSymbolAddress((void**)&mp,   g_m);
    cudaGetSymbolAddress((void**)&xqh,  g_xq_h);
    cudaGetSymbolAddress((void**)&xkvh, g_xkv_h);
    cudaGetSymbolAddress((void**)&atth, g_att_h);
    cudaGetSymbolAddress((void**)&wTh,  g_wT_h);

    cudaFuncSetAttribute(gemm_h, cudaFuncAttributeMaxDynamicSharedMemorySize, GEMM_SMEM);

    const int M = B_ * N0_;
    const float scale = 0.125f;

    mask_init<<<(B_ * N0_ + 255) / 256, 256>>>(kmask, mp, B_ * N0_);

    int n4 = M * D_ / 4;
    cvt_x<<<(n4 + 255) / 256, 256>>>(inputs_q,  xqh,  n4);
    cvt_x<<<(n4 + 255) / 256, 256>>>(inputs_kv, xkvh, n4);
    dim3 wtg(D_ / 32, D_ / 32, 4);
    cvt_wT<<<wtg, dim3(32, 8)>>>(Wq, Wk, Wv, Wo, wTh);

    dim3 gemmGrid(D_ / 128, M / 128);
    const size_t WSZ = (size_t)D_ * D_;
    gemm_h<<<gemmGrid, 256, GEMM_SMEM>>>(xqh,  wTh,           nullptr, qph, M, D_, D_, scale, bq, nullptr);
    gemm_h<<<gemmGrid, 256, GEMM_SMEM>>>(xkvh, wTh + WSZ,     nullptr, kph, M, D_, D_, 1.f, bk, nullptr);
    gemm_h<<<gemmGrid, 256, GEMM_SMEM>>>(xkvh, wTh + 2 * WSZ, nullptr, vph, M, D_, D_, 1.f, bv, kmask);

    // one-pass pyramid coarsen: 2 launches total
    dim3 ctg(16, 64, 12);
    coarsen_tree<<<ctg, 256>>>(qph, kph, vph);
    coarsen_mask_tree<<<dim3(64, B_), 128>>>(mp);

    // all 8 attention levels in ONE launch
    dim3 ag(510, H_, B_);
    hier_attn_all<<<ag, 128>>>(qph, kph, vph, mp, rpb, numh, denp);

    combine<<<B_ * N0_, 256>>>(numh, denp, qmask, atth);

    gemm_h<<<gemmGrid, 256, GEMM_SMEM>>>(atth, wTh + 3 * WSZ, out, nullptr, M, D_, D_, 1.f, bo, nullptr);
}